// round 9
// baseline (speedup 1.0000x reference)
#include <cuda_runtime.h>
#include <cuda_bf16.h>
#include <math.h>
#include <stdint.h>

#define N_NODES 50000
#define N_EDGES 500000
#define N_ET    (N_NODES + N_EDGES)   // 550000 edges incl. self-loops
#define NB_SCAN ((N_NODES + 255) / 256)   // 196 scan blocks

// ---------------- static scratch (no allocations allowed) ----------------
__device__ float g_xl1[N_NODES * 128];
__device__ float g_xr1[N_NODES * 128];
__device__ __nv_bfloat16 g_hhi[N_NODES * 128];
__device__ __nv_bfloat16 g_hlo[N_NODES * 128];
__device__ float g_xl2[N_NODES * 64];
__device__ float g_xr2[N_NODES * 64];
__device__ int   g_cnt   [N_NODES];
__device__ int   g_start [N_NODES + 1];
__device__ int   g_cursor[N_NODES];
__device__ int   g_sorted[N_ET];
__device__ int   g_bsum  [256];
// bf16 weight images, plain [n][k] row-major (ldmatrix-native for B operand)
__device__ __nv_bfloat16 g_B1hi[256 * 128];
__device__ __nv_bfloat16 g_B1lo[256 * 128];
__device__ __nv_bfloat16 g_B2hi[128 * 128];
__device__ __nv_bfloat16 g_B2lo[128 * 128];

// ---------------- counting sort of edges by destination ----------------
__global__ void zero_cnt_k() {
    for (int i = blockIdx.x * blockDim.x + threadIdx.x; i < N_NODES;
         i += gridDim.x * blockDim.x)
        g_cnt[i] = 0;
}
__device__ __forceinline__ int edge_dst(const int* __restrict__ ei, int e) {
    return (e < N_EDGES) ? ei[N_EDGES + e] : (e - N_EDGES);
}
__device__ __forceinline__ int edge_src(const int* __restrict__ ei, int e) {
    return (e < N_EDGES) ? ei[e] : (e - N_EDGES);
}
__global__ void hist_k(const int* __restrict__ ei) {
    int e = blockIdx.x * blockDim.x + threadIdx.x;
    if (e < N_ET) atomicAdd(&g_cnt[edge_dst(ei, e)], 1);
}

// ---------------- three-phase multi-block exclusive scan ----------------
__global__ void scan1_k() {               // per-block reduction
    __shared__ int sh[256];
    int i = blockIdx.x * 256 + threadIdx.x;
    int v = (i < N_NODES) ? g_cnt[i] : 0;
    sh[threadIdx.x] = v;
    __syncthreads();
    #pragma unroll
    for (int d = 128; d > 0; d >>= 1) {
        if (threadIdx.x < d) sh[threadIdx.x] += sh[threadIdx.x + d];
        __syncthreads();
    }
    if (threadIdx.x == 0) g_bsum[blockIdx.x] = sh[0];
}
__global__ void scan2_k() {               // scan the 196 block sums
    __shared__ int sh[256];
    int t = threadIdx.x;
    int v = (t < NB_SCAN) ? g_bsum[t] : 0;
    sh[t] = v;
    __syncthreads();
    #pragma unroll
    for (int d = 1; d < 256; d <<= 1) {
        int u = (t >= d) ? sh[t - d] : 0;
        __syncthreads();
        sh[t] += u;
        __syncthreads();
    }
    if (t < NB_SCAN) g_bsum[t] = sh[t] - v;   // exclusive
    if (t == 0) g_start[N_NODES] = N_ET;
}
__global__ void scan3_k() {               // per-block exclusive scan + offset
    __shared__ int sh[256];
    int t = threadIdx.x;
    int i = blockIdx.x * 256 + t;
    int v = (i < N_NODES) ? g_cnt[i] : 0;
    sh[t] = v;
    __syncthreads();
    #pragma unroll
    for (int d = 1; d < 256; d <<= 1) {
        int u = (t >= d) ? sh[t - d] : 0;
        __syncthreads();
        sh[t] += u;
        __syncthreads();
    }
    int ex = sh[t] - v + g_bsum[blockIdx.x];
    if (i < N_NODES) { g_start[i] = ex; g_cursor[i] = ex; }
}

__global__ void scatter_k(const int* __restrict__ ei) {
    int e = blockIdx.x * blockDim.x + threadIdx.x;
    if (e < N_ET) {
        int d = edge_dst(ei, e);
        int s = edge_src(ei, e);
        int pos = atomicAdd(&g_cursor[d], 1);
        g_sorted[pos] = s;
    }
}

// ---------------- weight -> bf16 hi/lo images, [n][k] row-major ----------
__global__ void bimg_k(const float* __restrict__ W1l, const float* __restrict__ W1r,
                       const float* __restrict__ W2l, const float* __restrict__ W2r) {
    int t = blockIdx.x * blockDim.x + threadIdx.x;
    if (t < 256 * 128) {                    // layer 1
        int n = t >> 7, k = t & 127;
        float v = (n < 128) ? W1l[k * 128 + n] : W1r[k * 128 + (n - 128)];
        __nv_bfloat16 h = __float2bfloat16_rn(v);
        g_B1hi[n * 128 + k] = h;
        g_B1lo[n * 128 + k] = __float2bfloat16_rn(v - __bfloat162float(h));
    } else if (t < 256 * 128 + 128 * 128) { // layer 2
        int t2 = t - 256 * 128;
        int n = t2 >> 7, k = t2 & 127;
        float v = (n < 64) ? W2l[k * 64 + n] : W2r[k * 64 + (n - 64)];
        __nv_bfloat16 h = __float2bfloat16_rn(v);
        g_B2hi[n * 128 + k] = h;
        g_B2lo[n * 128 + k] = __float2bfloat16_rn(v - __bfloat162float(h));
    }
}

// ---------------- mma.sync helpers (sm_80 baseline, works on sm_103) -----
__device__ __forceinline__ void ldsm_x4(uint32_t* r, uint32_t addr) {
    asm volatile("ldmatrix.sync.aligned.m8n8.x4.shared.b16 {%0,%1,%2,%3}, [%4];"
        : "=r"(r[0]), "=r"(r[1]), "=r"(r[2]), "=r"(r[3]) : "r"(addr));
}
__device__ __forceinline__ void mma_bf16(float* d, const uint32_t* a,
                                         uint32_t b0, uint32_t b1) {
    asm volatile("mma.sync.aligned.m16n8k16.row.col.f32.bf16.bf16.f32 "
        "{%0,%1,%2,%3}, {%4,%5,%6,%7}, {%8,%9}, {%0,%1,%2,%3};"
        : "+f"(d[0]), "+f"(d[1]), "+f"(d[2]), "+f"(d[3])
        : "r"(a[0]), "r"(a[1]), "r"(a[2]), "r"(a[3]), "r"(b0), "r"(b1));
}

// ---------------- HMMA split-bf16 dual GEMM ----------------
// D[128, 128-chunk] = Ahi@Bhi + Ahi@Blo + Alo@Bhi, fp32 accum.
// SMEM rows padded to 136 bf16 (272 B) for conflict-free ldmatrix.
template <int HALF, bool CONVERT>
__global__ void __launch_bounds__(256, 1)
gemm_tc_k(const float* __restrict__ xf,
          const __nv_bfloat16* __restrict__ ahi_g,
          const __nv_bfloat16* __restrict__ alo_g,
          const __nv_bfloat16* __restrict__ bhi_img,
          const __nv_bfloat16* __restrict__ blo_img,
          float* __restrict__ xl, float* __restrict__ xr) {
    extern __shared__ char smem[];
    constexpr int STRB = 272;                 // 136 bf16 per row
    constexpr int A_HI = 0;
    constexpr int A_LO = A_HI + 128 * STRB;   // 34816
    constexpr int B_HI = A_LO + 128 * STRB;
    constexpr int B_LO = B_HI + 128 * STRB;
    const int tid = threadIdx.x, wid = tid >> 5, lane = tid & 31;
    const int row0 = blockIdx.x * 128;
    const int nh   = blockIdx.y;
    uint32_t sb;
    asm("{ .reg .u64 t; cvta.to.shared.u64 t, %1; cvt.u32.u64 %0, t; }"
        : "=r"(sb) : "l"(smem));

    // ---- B tiles: row copy with padding ----
    {
        const uint4* s1 = (const uint4*)bhi_img;
        const uint4* s2 = (const uint4*)blo_img;
        for (int i = tid; i < 128 * 16; i += 256) {
            int r = i >> 4, seg = i & 15;
            *(uint4*)(smem + B_HI + r * STRB + seg * 16) = s1[(nh * 128 + r) * 16 + seg];
            *(uint4*)(smem + B_LO + r * STRB + seg * 16) = s2[(nh * 128 + r) * 16 + seg];
        }
    }
    // ---- A tiles ----
    if (CONVERT) {
        const float4* xt = (const float4*)(xf + (size_t)row0 * 128);
        for (int idx = tid; idx < 4096; idx += 256) {
            int r = idx >> 5, k4 = idx & 31, c0 = k4 * 4;
            float4 v = make_float4(0.f, 0.f, 0.f, 0.f);
            if (row0 + r < N_NODES) v = xt[idx];
            __nv_bfloat16 h0 = __float2bfloat16_rn(v.x);
            __nv_bfloat16 h1 = __float2bfloat16_rn(v.y);
            __nv_bfloat16 h2 = __float2bfloat16_rn(v.z);
            __nv_bfloat16 h3 = __float2bfloat16_rn(v.w);
            ushort hh[4] = { __bfloat16_as_ushort(h0), __bfloat16_as_ushort(h1),
                             __bfloat16_as_ushort(h2), __bfloat16_as_ushort(h3) };
            ushort ll[4] = {
                __bfloat16_as_ushort(__float2bfloat16_rn(v.x - __bfloat162float(h0))),
                __bfloat16_as_ushort(__float2bfloat16_rn(v.y - __bfloat162float(h1))),
                __bfloat16_as_ushort(__float2bfloat16_rn(v.z - __bfloat162float(h2))),
                __bfloat16_as_ushort(__float2bfloat16_rn(v.w - __bfloat162float(h3))) };
            *(uint2*)(smem + A_HI + r * STRB + c0 * 2) = *(const uint2*)hh;
            *(uint2*)(smem + A_LO + r * STRB + c0 * 2) = *(const uint2*)ll;
        }
    } else {
        const uint4* s1 = (const uint4*)ahi_g;
        const uint4* s2 = (const uint4*)alo_g;
        for (int idx = tid; idx < 2048; idx += 256) {
            int r = idx >> 4, seg = idx & 15;
            uint4 v1 = make_uint4(0u, 0u, 0u, 0u), v2 = v1;
            if (row0 + r < N_NODES) {
                v1 = s1[(size_t)(row0 + r) * 16 + seg];
                v2 = s2[(size_t)(row0 + r) * 16 + seg];
            }
            *(uint4*)(smem + A_HI + r * STRB + seg * 16) = v1;
            *(uint4*)(smem + A_LO + r * STRB + seg * 16) = v2;
        }
    }
    __syncthreads();

    // ---- mainloop: per warp, 16 rows x 128 cols ----
    const int m0 = wid * 16;
    uint32_t aRow = m0 + (lane & 15);
    uint32_t aCol = (lane >> 4) * 16;              // bytes
    uint32_t aAddrH = sb + A_HI + aRow * STRB + aCol;
    uint32_t aAddrL = sb + A_LO + aRow * STRB + aCol;
    int g = lane >> 3;
    uint32_t bRow = (lane & 7) + ((g & 2) << 2);   // +8 for g>=2
    uint32_t bCol = (g & 1) * 16;                  // bytes
    uint32_t bAddrH = sb + B_HI + bRow * STRB + bCol;
    uint32_t bAddrL = sb + B_LO + bRow * STRB + bCol;

    float acc[16][4];
    #pragma unroll
    for (int i = 0; i < 16; i++)
        #pragma unroll
        for (int j = 0; j < 4; j++) acc[i][j] = 0.f;

    #pragma unroll 1
    for (int ks = 0; ks < 8; ks++) {
        uint32_t ka = ks * 32;                     // 16 bf16 = 32 bytes
        uint32_t ah[4], al[4];
        ldsm_x4(ah, aAddrH + ka);
        ldsm_x4(al, aAddrL + ka);
        #pragma unroll
        for (int nt2 = 0; nt2 < 8; nt2++) {
            uint32_t off = nt2 * (16 * STRB) + ka;
            uint32_t bh[4], bl[4];
            ldsm_x4(bh, bAddrH + off);
            ldsm_x4(bl, bAddrL + off);
            mma_bf16(acc[nt2 * 2],     ah, bh[0], bh[1]);
            mma_bf16(acc[nt2 * 2],     ah, bl[0], bl[1]);
            mma_bf16(acc[nt2 * 2],     al, bh[0], bh[1]);
            mma_bf16(acc[nt2 * 2 + 1], ah, bh[2], bh[3]);
            mma_bf16(acc[nt2 * 2 + 1], ah, bl[2], bl[3]);
            mma_bf16(acc[nt2 * 2 + 1], al, bh[2], bh[3]);
        }
    }

    // ---- epilogue: direct float2 stores (full 32B sectors) ----
    const int rq = lane >> 2;           // 0..7
    const int cq = (lane & 3) * 2;
    const int r0g = row0 + m0 + rq;
    const int r1g = r0g + 8;
    #pragma unroll
    for (int nt = 0; nt < 16; nt++) {
        int gc = nh * 128 + nt * 8 + cq;
        float2 v0 = make_float2(acc[nt][0], acc[nt][1]);
        float2 v1 = make_float2(acc[nt][2], acc[nt][3]);
        if (gc < HALF) {
            if (r0g < N_NODES) *(float2*)&xl[(size_t)r0g * HALF + gc] = v0;
            if (r1g < N_NODES) *(float2*)&xl[(size_t)r1g * HALF + gc] = v1;
        } else {
            int g2 = gc - HALF;
            if (r0g < N_NODES) *(float2*)&xr[(size_t)r0g * HALF + g2] = v0;
            if (r1g < N_NODES) *(float2*)&xr[(size_t)r1g * HALF + g2] = v1;
        }
    }
}

// ---------------- fused GATv2 softmax + aggregation (one warp per node) --
// Single pass, no max-subtraction. ILP-2: two edges per iteration with
// interleaved score/shfl/exp chains + prefetch of the next pair (MLP=4).
template <int H, int C, int MODE>
__global__ void agg_k(const float* __restrict__ xl, const float* __restrict__ xr,
                      const float* __restrict__ att, const float* __restrict__ bias,
                      float* __restrict__ outf,
                      __nv_bfloat16* __restrict__ ohi, __nv_bfloat16* __restrict__ olo) {
    constexpr int HC  = H * C;
    constexpr int VEC = HC / 32;       // 4 (layer1) or 2 (layer2)
    constexpr int LPH = C / VEC;       // lanes per head
    const int lane = threadIdx.x & 31;
    const int d = blockIdx.x * (blockDim.x >> 5) + (threadIdx.x >> 5);
    if (d >= N_NODES) return;
    const int base = lane * VEC;

    float xrv[VEC], attv[VEC];
    #pragma unroll
    for (int v = 0; v < VEC; v++) {
        xrv[v]  = xr[(size_t)d * HC + base + v];
        attv[v] = att[base + v];
    }
    const int s0 = g_start[d], s1 = g_start[d + 1];
    const int n  = s1 - s0;
    const int npair = n >> 1;

    float acc[VEC];
    #pragma unroll
    for (int v = 0; v < VEC; v++) acc[v] = 0.f;
    float den = 0.f;

    // prefetch registers for the current pair
    float c0[VEC], c1[VEC];
    if (npair > 0) {
        const float* p0 = xl + (size_t)g_sorted[s0]     * HC + base;
        const float* p1 = xl + (size_t)g_sorted[s0 + 1] * HC + base;
        if (VEC == 4) {
            float4 t0 = *(const float4*)p0;
            float4 t1 = *(const float4*)p1;
            c0[0]=t0.x; c0[1]=t0.y; c0[2]=t0.z; c0[3]=t0.w;
            c1[0]=t1.x; c1[1]=t1.y; c1[2]=t1.z; c1[3]=t1.w;
        } else {
            float2 t0 = *(const float2*)p0;
            float2 t1 = *(const float2*)p1;
            c0[0]=t0.x; c0[1]=t0.y;
            c1[0]=t1.x; c1[1]=t1.y;
        }
    }

    for (int k2 = 0; k2 < npair; k2++) {
        float x0[VEC], x1[VEC];
        #pragma unroll
        for (int v = 0; v < VEC; v++) { x0[v] = c0[v]; x1[v] = c1[v]; }

        if (k2 + 1 < npair) {           // prefetch next pair
            int jn = s0 + 2 * (k2 + 1);
            const float* p0 = xl + (size_t)g_sorted[jn]     * HC + base;
            const float* p1 = xl + (size_t)g_sorted[jn + 1] * HC + base;
            if (VEC == 4) {
                float4 t0 = *(const float4*)p0;
                float4 t1 = *(const float4*)p1;
                c0[0]=t0.x; c0[1]=t0.y; c0[2]=t0.z; c0[3]=t0.w;
                c1[0]=t1.x; c1[1]=t1.y; c1[2]=t1.z; c1[3]=t1.w;
            } else {
                float2 t0 = *(const float2*)p0;
                float2 t1 = *(const float2*)p1;
                c0[0]=t0.x; c0[1]=t0.y;
                c1[0]=t1.x; c1[1]=t1.y;
            }
        }

        float sA = 0.f, sB = 0.f;
        #pragma unroll
        for (int v = 0; v < VEC; v++) {
            float m0 = x0[v] + xrv[v];
            float m1 = x1[v] + xrv[v];
            m0 = (m0 > 0.f) ? m0 : 0.2f * m0;
            m1 = (m1 > 0.f) ? m1 : 0.2f * m1;
            sA = fmaf(m0, attv[v], sA);
            sB = fmaf(m1, attv[v], sB);
        }
        #pragma unroll
        for (int w = LPH >> 1; w > 0; w >>= 1) {   // interleaved chains
            sA += __shfl_xor_sync(0xffffffffu, sA, w);
            sB += __shfl_xor_sync(0xffffffffu, sB, w);
        }
        float pA = __expf(sA);
        float pB = __expf(sB);
        den += pA + pB;
        #pragma unroll
        for (int v = 0; v < VEC; v++)
            acc[v] = fmaf(pB, x1[v], fmaf(pA, x0[v], acc[v]));
    }

    if (n & 1) {                        // odd tail edge
        const float* xp = xl + (size_t)g_sorted[s1 - 1] * HC + base;
        float xv[VEC];
        if (VEC == 4) {
            float4 t = *(const float4*)xp;
            xv[0]=t.x; xv[1]=t.y; xv[2]=t.z; xv[3]=t.w;
        } else {
            float2 t = *(const float2*)xp;
            xv[0]=t.x; xv[1]=t.y;
        }
        float s = 0.f;
        #pragma unroll
        for (int v = 0; v < VEC; v++) {
            float m = xv[v] + xrv[v];
            m = (m > 0.f) ? m : 0.2f * m;
            s = fmaf(m, attv[v], s);
        }
        #pragma unroll
        for (int w = LPH >> 1; w > 0; w >>= 1)
            s += __shfl_xor_sync(0xffffffffu, s, w);
        float p = __expf(s);
        den += p;
        #pragma unroll
        for (int v = 0; v < VEC; v++) acc[v] = fmaf(p, xv[v], acc[v]);
    }

    const float inv = 1.0f / den;       // self-loop guarantees den > 0
    if (MODE == 0) {
        #pragma unroll
        for (int v = 0; v < VEC; v++)
            outf[(size_t)d * HC + base + v] = acc[v] * inv + bias[base + v];
    } else {
        ushort hh[VEC], ll[VEC];
        #pragma unroll
        for (int v = 0; v < VEC; v++) {
            float r = acc[v] * inv + bias[base + v];
            r = (r > 0.f) ? r : (__expf(r) - 1.0f);   // ELU
            __nv_bfloat16 hb = __float2bfloat16_rn(r);
            hh[v] = __bfloat16_as_ushort(hb);
            ll[v] = __bfloat16_as_ushort(__float2bfloat16_rn(r - __bfloat162float(hb)));
        }
        size_t o = ((size_t)d * HC + base) >> 2;      // VEC==4: uint2 granules
        ((uint2*)ohi)[o] = *(const uint2*)hh;
        ((uint2*)olo)[o] = *(const uint2*)ll;
    }
}

// ---------------- launch ----------------
extern "C" void kernel_launch(void* const* d_in, const int* in_sizes, int n_in,
                              void* d_out, int out_size) {
    const float* x    = (const float*)d_in[0];
    const int*   ei   = (const int*)  d_in[1];
    const float* W1l  = (const float*)d_in[2];
    const float* W1r  = (const float*)d_in[3];
    const float* att1 = (const float*)d_in[4];
    const float* b1   = (const float*)d_in[5];
    const float* W2l  = (const float*)d_in[6];
    const float* W2r  = (const float*)d_in[7];
    const float* att2 = (const float*)d_in[8];
    const float* b2   = (const float*)d_in[9];
    float* out = (float*)d_out;

    float *xl1, *xr1, *xl2, *xr2;
    __nv_bfloat16 *hhi, *hlo, *b1hi, *b1lo, *b2hi, *b2lo;
    cudaGetSymbolAddress((void**)&xl1, g_xl1);
    cudaGetSymbolAddress((void**)&xr1, g_xr1);
    cudaGetSymbolAddress((void**)&hhi, g_hhi);
    cudaGetSymbolAddress((void**)&hlo, g_hlo);
    cudaGetSymbolAddress((void**)&xl2, g_xl2);
    cudaGetSymbolAddress((void**)&xr2, g_xr2);
    cudaGetSymbolAddress((void**)&b1hi, g_B1hi);
    cudaGetSymbolAddress((void**)&b1lo, g_B1lo);
    cudaGetSymbolAddress((void**)&b2hi, g_B2hi);
    cudaGetSymbolAddress((void**)&b2lo, g_B2lo);

    constexpr int SMEMB = 4 * 128 * 272;   // 139264
    cudaFuncSetAttribute(gemm_tc_k<128, true>,
                         cudaFuncAttributeMaxDynamicSharedMemorySize, SMEMB);
    cudaFuncSetAttribute(gemm_tc_k<64, false>,
                         cudaFuncAttributeMaxDynamicSharedMemorySize, SMEMB);

    const int ETB = (N_ET + 255) / 256;
    const int GT  = (N_NODES + 127) / 128;   // 391 gemm tiles

    // edge CSR (sorted by dst) — parallel 3-phase scan
    zero_cnt_k<<<148, 256>>>();
    hist_k<<<ETB, 256>>>(ei);
    bimg_k<<<192, 256>>>(W1l, W1r, W2l, W2r);
    scan1_k<<<NB_SCAN, 256>>>();
    scan2_k<<<1, 256>>>();
    scan3_k<<<NB_SCAN, 256>>>();
    scatter_k<<<ETB, 256>>>(ei);

    // layer 1
    gemm_tc_k<128, true><<<dim3(GT, 2), 256, SMEMB>>>(x, nullptr, nullptr,
                                                      b1hi, b1lo, xl1, xr1);
    agg_k<4, 32, 1><<<(N_NODES + 7) / 8, 256>>>(xl1, xr1, att1, b1,
                                                nullptr, hhi, hlo);
    // layer 2
    gemm_tc_k<64, false><<<dim3(GT, 1), 256, SMEMB>>>(nullptr, hhi, hlo,
                                                      b2hi, b2lo, xl2, xr2);
    agg_k<1, 64, 0><<<(N_NODES + 7) / 8, 256>>>(xl2, xr2, att2, b2,
                                                out, nullptr, nullptr);
}

// round 10
// speedup vs baseline: 1.1229x; 1.1229x over previous
#include <cuda_runtime.h>
#include <cuda_bf16.h>
#include <math.h>
#include <stdint.h>

#define N_NODES 50000
#define N_EDGES 500000
#define N_ET    (N_NODES + N_EDGES)   // 550000 edges incl. self-loops
#define NB_SCAN ((N_NODES + 255) / 256)   // 196 scan blocks

// ---------------- static scratch (no allocations allowed) ----------------
__device__ float g_xl1[N_NODES * 128];
__device__ float g_xr1[N_NODES * 128];
__device__ __nv_bfloat16 g_hhi[N_NODES * 128];
__device__ __nv_bfloat16 g_hlo[N_NODES * 128];
__device__ float g_xl2[N_NODES * 64];
__device__ float g_xr2[N_NODES * 64];
__device__ int   g_cnt   [N_NODES];
__device__ int   g_start [N_NODES + 1];
__device__ int   g_cursor[N_NODES];
__device__ int   g_sorted[N_ET];
__device__ int   g_bsum  [256];
// bf16 weight images, plain [n][k] row-major (ldmatrix-native for B operand)
__device__ __nv_bfloat16 g_B1hi[256 * 128];
__device__ __nv_bfloat16 g_B1lo[256 * 128];
__device__ __nv_bfloat16 g_B2hi[128 * 128];
__device__ __nv_bfloat16 g_B2lo[128 * 128];

// ---------------- counting sort of edges by destination ----------------
__global__ void zero_cnt_k() {
    for (int i = blockIdx.x * blockDim.x + threadIdx.x; i < N_NODES;
         i += gridDim.x * blockDim.x)
        g_cnt[i] = 0;
}
__device__ __forceinline__ int edge_dst(const int* __restrict__ ei, int e) {
    return (e < N_EDGES) ? ei[N_EDGES + e] : (e - N_EDGES);
}
__device__ __forceinline__ int edge_src(const int* __restrict__ ei, int e) {
    return (e < N_EDGES) ? ei[e] : (e - N_EDGES);
}
__global__ void hist_k(const int* __restrict__ ei) {
    int e = blockIdx.x * blockDim.x + threadIdx.x;
    if (e < N_ET) atomicAdd(&g_cnt[edge_dst(ei, e)], 1);
}

// ---------------- three-phase multi-block exclusive scan ----------------
__global__ void scan1_k() {               // per-block reduction
    __shared__ int sh[256];
    int i = blockIdx.x * 256 + threadIdx.x;
    int v = (i < N_NODES) ? g_cnt[i] : 0;
    sh[threadIdx.x] = v;
    __syncthreads();
    #pragma unroll
    for (int d = 128; d > 0; d >>= 1) {
        if (threadIdx.x < d) sh[threadIdx.x] += sh[threadIdx.x + d];
        __syncthreads();
    }
    if (threadIdx.x == 0) g_bsum[blockIdx.x] = sh[0];
}
__global__ void scan2_k() {               // scan the 196 block sums
    __shared__ int sh[256];
    int t = threadIdx.x;
    int v = (t < NB_SCAN) ? g_bsum[t] : 0;
    sh[t] = v;
    __syncthreads();
    #pragma unroll
    for (int d = 1; d < 256; d <<= 1) {
        int u = (t >= d) ? sh[t - d] : 0;
        __syncthreads();
        sh[t] += u;
        __syncthreads();
    }
    if (t < NB_SCAN) g_bsum[t] = sh[t] - v;   // exclusive
    if (t == 0) g_start[N_NODES] = N_ET;
}
__global__ void scan3_k() {               // per-block exclusive scan + offset
    __shared__ int sh[256];
    int t = threadIdx.x;
    int i = blockIdx.x * 256 + t;
    int v = (i < N_NODES) ? g_cnt[i] : 0;
    sh[t] = v;
    __syncthreads();
    #pragma unroll
    for (int d = 1; d < 256; d <<= 1) {
        int u = (t >= d) ? sh[t - d] : 0;
        __syncthreads();
        sh[t] += u;
        __syncthreads();
    }
    int ex = sh[t] - v + g_bsum[blockIdx.x];
    if (i < N_NODES) { g_start[i] = ex; g_cursor[i] = ex; }
}

__global__ void scatter_k(const int* __restrict__ ei) {
    int e = blockIdx.x * blockDim.x + threadIdx.x;
    if (e < N_ET) {
        int d = edge_dst(ei, e);
        int s = edge_src(ei, e);
        int pos = atomicAdd(&g_cursor[d], 1);
        g_sorted[pos] = s;
    }
}

// ---------------- weight -> bf16 hi/lo images, [n][k] row-major ----------
__global__ void bimg_k(const float* __restrict__ W1l, const float* __restrict__ W1r,
                       const float* __restrict__ W2l, const float* __restrict__ W2r) {
    int t = blockIdx.x * blockDim.x + threadIdx.x;
    if (t < 256 * 128) {                    // layer 1
        int n = t >> 7, k = t & 127;
        float v = (n < 128) ? W1l[k * 128 + n] : W1r[k * 128 + (n - 128)];
        __nv_bfloat16 h = __float2bfloat16_rn(v);
        g_B1hi[n * 128 + k] = h;
        g_B1lo[n * 128 + k] = __float2bfloat16_rn(v - __bfloat162float(h));
    } else if (t < 256 * 128 + 128 * 128) { // layer 2
        int t2 = t - 256 * 128;
        int n = t2 >> 7, k = t2 & 127;
        float v = (n < 64) ? W2l[k * 64 + n] : W2r[k * 64 + (n - 64)];
        __nv_bfloat16 h = __float2bfloat16_rn(v);
        g_B2hi[n * 128 + k] = h;
        g_B2lo[n * 128 + k] = __float2bfloat16_rn(v - __bfloat162float(h));
    }
}

// ---------------- mma.sync helpers (sm_80 baseline, works on sm_103) -----
__device__ __forceinline__ void ldsm_x4(uint32_t* r, uint32_t addr) {
    asm volatile("ldmatrix.sync.aligned.m8n8.x4.shared.b16 {%0,%1,%2,%3}, [%4];"
        : "=r"(r[0]), "=r"(r[1]), "=r"(r[2]), "=r"(r[3]) : "r"(addr));
}
__device__ __forceinline__ void mma_bf16(float* d, const uint32_t* a,
                                         uint32_t b0, uint32_t b1) {
    asm volatile("mma.sync.aligned.m16n8k16.row.col.f32.bf16.bf16.f32 "
        "{%0,%1,%2,%3}, {%4,%5,%6,%7}, {%8,%9}, {%0,%1,%2,%3};"
        : "+f"(d[0]), "+f"(d[1]), "+f"(d[2]), "+f"(d[3])
        : "r"(a[0]), "r"(a[1]), "r"(a[2]), "r"(a[3]), "r"(b0), "r"(b1));
}

// ---------------- HMMA split-bf16 dual GEMM ----------------
// D[128, NOUT] = Ahi@Bhi + Ahi@Blo + Alo@Bhi, fp32 accum.
// A tile loaded/converted ONCE; N processed in 128-wide serial passes
// reusing the B smem region. Cols [0,HALF) -> xl, rest -> xr.
// SMEM rows padded to 136 bf16 (272 B) for conflict-free ldmatrix.
template <int NOUT, int HALF, bool CONVERT>
__global__ void __launch_bounds__(256, 1)
gemm_tc_k(const float* __restrict__ xf,
          const __nv_bfloat16* __restrict__ ahi_g,
          const __nv_bfloat16* __restrict__ alo_g,
          const __nv_bfloat16* __restrict__ bhi_img,
          const __nv_bfloat16* __restrict__ blo_img,
          float* __restrict__ xl, float* __restrict__ xr) {
    extern __shared__ char smem[];
    constexpr int STRB = 272;                 // 136 bf16 per row
    constexpr int A_HI = 0;
    constexpr int A_LO = A_HI + 128 * STRB;   // 34816
    constexpr int B_HI = A_LO + 128 * STRB;
    constexpr int B_LO = B_HI + 128 * STRB;
    constexpr int NPASS = NOUT / 128;
    const int tid = threadIdx.x, wid = tid >> 5, lane = tid & 31;
    const int row0 = blockIdx.x * 128;
    uint32_t sb;
    asm("{ .reg .u64 t; cvta.to.shared.u64 t, %1; cvt.u32.u64 %0, t; }"
        : "=r"(sb) : "l"(smem));

    // ---- A tile (once) ----
    if (CONVERT) {
        const float4* xt = (const float4*)(xf + (size_t)row0 * 128);
        for (int idx = tid; idx < 4096; idx += 256) {
            int r = idx >> 5, k4 = idx & 31, c0 = k4 * 4;
            float4 v = make_float4(0.f, 0.f, 0.f, 0.f);
            if (row0 + r < N_NODES) v = xt[idx];
            __nv_bfloat16 h0 = __float2bfloat16_rn(v.x);
            __nv_bfloat16 h1 = __float2bfloat16_rn(v.y);
            __nv_bfloat16 h2 = __float2bfloat16_rn(v.z);
            __nv_bfloat16 h3 = __float2bfloat16_rn(v.w);
            ushort hh[4] = { __bfloat16_as_ushort(h0), __bfloat16_as_ushort(h1),
                             __bfloat16_as_ushort(h2), __bfloat16_as_ushort(h3) };
            ushort ll[4] = {
                __bfloat16_as_ushort(__float2bfloat16_rn(v.x - __bfloat162float(h0))),
                __bfloat16_as_ushort(__float2bfloat16_rn(v.y - __bfloat162float(h1))),
                __bfloat16_as_ushort(__float2bfloat16_rn(v.z - __bfloat162float(h2))),
                __bfloat16_as_ushort(__float2bfloat16_rn(v.w - __bfloat162float(h3))) };
            *(uint2*)(smem + A_HI + r * STRB + c0 * 2) = *(const uint2*)hh;
            *(uint2*)(smem + A_LO + r * STRB + c0 * 2) = *(const uint2*)ll;
        }
    } else {
        const uint4* s1 = (const uint4*)ahi_g;
        const uint4* s2 = (const uint4*)alo_g;
        for (int idx = tid; idx < 2048; idx += 256) {
            int r = idx >> 4, seg = idx & 15;
            uint4 v1 = make_uint4(0u, 0u, 0u, 0u), v2 = v1;
            if (row0 + r < N_NODES) {
                v1 = s1[(size_t)(row0 + r) * 16 + seg];
                v2 = s2[(size_t)(row0 + r) * 16 + seg];
            }
            *(uint4*)(smem + A_HI + r * STRB + seg * 16) = v1;
            *(uint4*)(smem + A_LO + r * STRB + seg * 16) = v2;
        }
    }

    // warp-tile addressing (fixed across passes)
    const int m0 = wid * 16;
    uint32_t aRow = m0 + (lane & 15);
    uint32_t aCol = (lane >> 4) * 16;              // bytes
    uint32_t aAddrH = sb + A_HI + aRow * STRB + aCol;
    uint32_t aAddrL = sb + A_LO + aRow * STRB + aCol;
    int g = lane >> 3;
    uint32_t bRow = (lane & 7) + ((g & 2) << 2);   // +8 for g>=2
    uint32_t bCol = (g & 1) * 16;                  // bytes
    uint32_t bAddrH = sb + B_HI + bRow * STRB + bCol;
    uint32_t bAddrL = sb + B_LO + bRow * STRB + bCol;
    const int rq = lane >> 2;
    const int cq = (lane & 3) * 2;
    const int r0g = row0 + m0 + rq;
    const int r1g = r0g + 8;

    #pragma unroll 1
    for (int nh = 0; nh < NPASS; nh++) {
        // ---- B tiles for this N pass ----
        if (nh) __syncthreads();          // prior pass done reading B
        {
            const uint4* s1 = (const uint4*)bhi_img;
            const uint4* s2 = (const uint4*)blo_img;
            for (int i = tid; i < 128 * 16; i += 256) {
                int r = i >> 4, seg = i & 15;
                *(uint4*)(smem + B_HI + r * STRB + seg * 16) = s1[(nh * 128 + r) * 16 + seg];
                *(uint4*)(smem + B_LO + r * STRB + seg * 16) = s2[(nh * 128 + r) * 16 + seg];
            }
        }
        __syncthreads();

        float acc[16][4];
        #pragma unroll
        for (int i = 0; i < 16; i++)
            #pragma unroll
            for (int j = 0; j < 4; j++) acc[i][j] = 0.f;

        #pragma unroll 1
        for (int ks = 0; ks < 8; ks++) {
            uint32_t ka = ks * 32;                 // 16 bf16 = 32 bytes
            uint32_t ah[4], al[4];
            ldsm_x4(ah, aAddrH + ka);
            ldsm_x4(al, aAddrL + ka);
            #pragma unroll
            for (int nt2 = 0; nt2 < 8; nt2++) {
                uint32_t off = nt2 * (16 * STRB) + ka;
                uint32_t bh[4], bl[4];
                ldsm_x4(bh, bAddrH + off);
                ldsm_x4(bl, bAddrL + off);
                mma_bf16(acc[nt2 * 2],     ah, bh[0], bh[1]);
                mma_bf16(acc[nt2 * 2],     ah, bl[0], bl[1]);
                mma_bf16(acc[nt2 * 2],     al, bh[0], bh[1]);
                mma_bf16(acc[nt2 * 2 + 1], ah, bh[2], bh[3]);
                mma_bf16(acc[nt2 * 2 + 1], ah, bl[2], bl[3]);
                mma_bf16(acc[nt2 * 2 + 1], al, bh[2], bh[3]);
            }
        }

        // ---- epilogue: direct float2 stores (full 32B sectors) ----
        #pragma unroll
        for (int nt = 0; nt < 16; nt++) {
            int gc = nh * 128 + nt * 8 + cq;
            float2 v0 = make_float2(acc[nt][0], acc[nt][1]);
            float2 v1 = make_float2(acc[nt][2], acc[nt][3]);
            if (gc < HALF) {
                if (r0g < N_NODES) *(float2*)&xl[(size_t)r0g * HALF + gc] = v0;
                if (r1g < N_NODES) *(float2*)&xl[(size_t)r1g * HALF + gc] = v1;
            } else {
                int g2 = gc - HALF;
                if (r0g < N_NODES) *(float2*)&xr[(size_t)r0g * HALF + g2] = v0;
                if (r1g < N_NODES) *(float2*)&xr[(size_t)r1g * HALF + g2] = v1;
            }
        }
    }
}

// ---------------- fused GATv2 softmax + aggregation (one warp per node) --
// Single pass, no max-subtraction (scores O(5), fp32-exp safe).
// MODE 0: fp32 out + bias. MODE 1: bias + ELU, output split bf16 hi/lo.
template <int H, int C, int MODE>
__global__ void agg_k(const float* __restrict__ xl, const float* __restrict__ xr,
                      const float* __restrict__ att, const float* __restrict__ bias,
                      float* __restrict__ outf,
                      __nv_bfloat16* __restrict__ ohi, __nv_bfloat16* __restrict__ olo) {
    constexpr int HC  = H * C;
    constexpr int VEC = HC / 32;       // 4 (layer1) or 2 (layer2)
    constexpr int LPH = C / VEC;       // lanes per head
    const int lane = threadIdx.x & 31;
    const int d = blockIdx.x * (blockDim.x >> 5) + (threadIdx.x >> 5);
    if (d >= N_NODES) return;
    const int base = lane * VEC;

    float xrv[VEC], attv[VEC];
    #pragma unroll
    for (int v = 0; v < VEC; v++) {
        xrv[v]  = xr[(size_t)d * HC + base + v];
        attv[v] = att[base + v];
    }
    const int s0 = g_start[d], s1 = g_start[d + 1];

    float acc[VEC];
    #pragma unroll
    for (int v = 0; v < VEC; v++) acc[v] = 0.f;
    float den = 0.f;

    float xn[VEC];
    if (s0 < s1) {
        const float* xp = xl + (size_t)g_sorted[s0] * HC + base;
        if (VEC == 4) {
            float4 t = *(const float4*)xp;
            xn[0] = t.x; xn[1] = t.y; xn[2] = t.z; xn[3] = t.w;
        } else {
            float2 t = *(const float2*)xp;
            xn[0] = t.x; xn[1] = t.y;
        }
    }
    for (int j = s0; j < s1; j++) {
        float xv[VEC];
        #pragma unroll
        for (int v = 0; v < VEC; v++) xv[v] = xn[v];
        if (j + 1 < s1) {
            const float* xp = xl + (size_t)g_sorted[j + 1] * HC + base;
            if (VEC == 4) {
                float4 t = *(const float4*)xp;
                xn[0] = t.x; xn[1] = t.y; xn[2] = t.z; xn[3] = t.w;
            } else {
                float2 t = *(const float2*)xp;
                xn[0] = t.x; xn[1] = t.y;
            }
        }
        float s = 0.f;
        #pragma unroll
        for (int v = 0; v < VEC; v++) {
            float m = xv[v] + xrv[v];
            m = (m > 0.f) ? m : 0.2f * m;      // leaky_relu
            s = fmaf(m, attv[v], s);
        }
        #pragma unroll
        for (int w = LPH >> 1; w > 0; w >>= 1)
            s += __shfl_xor_sync(0xffffffffu, s, w);
        float p = __expf(s);
        den += p;
        #pragma unroll
        for (int v = 0; v < VEC; v++) acc[v] = fmaf(p, xv[v], acc[v]);
    }

    const float inv = 1.0f / den;       // self-loop guarantees den > 0
    if (MODE == 0) {
        #pragma unroll
        for (int v = 0; v < VEC; v++)
            outf[(size_t)d * HC + base + v] = acc[v] * inv + bias[base + v];
    } else {
        ushort hh[VEC], ll[VEC];
        #pragma unroll
        for (int v = 0; v < VEC; v++) {
            float r = acc[v] * inv + bias[base + v];
            r = (r > 0.f) ? r : (__expf(r) - 1.0f);   // ELU
            __nv_bfloat16 hb = __float2bfloat16_rn(r);
            hh[v] = __bfloat16_as_ushort(hb);
            ll[v] = __bfloat16_as_ushort(__float2bfloat16_rn(r - __bfloat162float(hb)));
        }
        size_t o = ((size_t)d * HC + base) >> 2;      // VEC==4: uint2 granules
        ((uint2*)ohi)[o] = *(const uint2*)hh;
        ((uint2*)olo)[o] = *(const uint2*)ll;
    }
}

// ---------------- launch ----------------
extern "C" void kernel_launch(void* const* d_in, const int* in_sizes, int n_in,
                              void* d_out, int out_size) {
    const float* x    = (const float*)d_in[0];
    const int*   ei   = (const int*)  d_in[1];
    const float* W1l  = (const float*)d_in[2];
    const float* W1r  = (const float*)d_in[3];
    const float* att1 = (const float*)d_in[4];
    const float* b1   = (const float*)d_in[5];
    const float* W2l  = (const float*)d_in[6];
    const float* W2r  = (const float*)d_in[7];
    const float* att2 = (const float*)d_in[8];
    const float* b2   = (const float*)d_in[9];
    float* out = (float*)d_out;

    float *xl1, *xr1, *xl2, *xr2;
    __nv_bfloat16 *hhi, *hlo, *b1hi, *b1lo, *b2hi, *b2lo;
    cudaGetSymbolAddress((void**)&xl1, g_xl1);
    cudaGetSymbolAddress((void**)&xr1, g_xr1);
    cudaGetSymbolAddress((void**)&hhi, g_hhi);
    cudaGetSymbolAddress((void**)&hlo, g_hlo);
    cudaGetSymbolAddress((void**)&xl2, g_xl2);
    cudaGetSymbolAddress((void**)&xr2, g_xr2);
    cudaGetSymbolAddress((void**)&b1hi, g_B1hi);
    cudaGetSymbolAddress((void**)&b1lo, g_B1lo);
    cudaGetSymbolAddress((void**)&b2hi, g_B2hi);
    cudaGetSymbolAddress((void**)&b2lo, g_B2lo);

    constexpr int SMEMB = 4 * 128 * 272;   // 139264
    cudaFuncSetAttribute(gemm_tc_k<256, 128, true>,
                         cudaFuncAttributeMaxDynamicSharedMemorySize, SMEMB);
    cudaFuncSetAttribute(gemm_tc_k<128, 64, false>,
                         cudaFuncAttributeMaxDynamicSharedMemorySize, SMEMB);

    const int ETB = (N_ET + 255) / 256;
    const int GT  = (N_NODES + 127) / 128;   // 391 gemm tiles

    // NOTE: gemm1 placed 4th — the ncu capture slot — for visibility.
    zero_cnt_k<<<148, 256>>>();
    hist_k<<<ETB, 256>>>(ei);
    bimg_k<<<192, 256>>>(W1l, W1r, W2l, W2r);
    gemm_tc_k<256, 128, true><<<GT, 256, SMEMB>>>(x, nullptr, nullptr,
                                                  b1hi, b1lo, xl1, xr1);
    scan1_k<<<NB_SCAN, 256>>>();
    scan2_k<<<1, 256>>>();
    scan3_k<<<NB_SCAN, 256>>>();
    scatter_k<<<ETB, 256>>>(ei);

    agg_k<4, 32, 1><<<(N_NODES + 7) / 8, 256>>>(xl1, xr1, att1, b1,
                                                nullptr, hhi, hlo);
    gemm_tc_k<128, 64, false><<<GT, 256, SMEMB>>>(nullptr, hhi, hlo,
                                                  b2hi, b2lo, xl2, xr2);
    agg_k<1, 64, 0><<<(N_NODES + 7) / 8, 256>>>(xl2, xr2, att2, b2,
                                                out, nullptr, nullptr);
}

// round 11
// speedup vs baseline: 1.2007x; 1.0693x over previous
#include <cuda_runtime.h>
#include <cuda_bf16.h>
#include <math.h>
#include <stdint.h>

#define N_NODES 50000
#define N_EDGES 500000
#define N_ET    (N_NODES + N_EDGES)   // 550000 edges incl. self-loops
#define NB_SCAN ((N_NODES + 255) / 256)   // 196 scan blocks

// ---------------- static scratch (no allocations allowed) ----------------
__device__ float g_xl1[N_NODES * 128];
__device__ float g_xr1[N_NODES * 128];
__device__ __nv_bfloat16 g_hhi[N_NODES * 128];
__device__ __nv_bfloat16 g_hlo[N_NODES * 128];
__device__ float g_xl2[N_NODES * 64];
__device__ float g_xr2[N_NODES * 64];
__device__ int   g_cnt   [N_NODES];
__device__ int   g_start [N_NODES + 1];
__device__ int   g_cursor[N_NODES];
__device__ int   g_sorted[N_ET];
__device__ int   g_bsum  [256];
// bf16 weight images, plain [n][k] row-major (ldmatrix-native for B operand)
__device__ __nv_bfloat16 g_B1hi[256 * 128];
__device__ __nv_bfloat16 g_B1lo[256 * 128];
__device__ __nv_bfloat16 g_B2hi[128 * 128];
__device__ __nv_bfloat16 g_B2lo[128 * 128];

// ---------------- counting sort of edges by destination ----------------
__global__ void zero_cnt_k() {
    for (int i = blockIdx.x * blockDim.x + threadIdx.x; i < N_NODES;
         i += gridDim.x * blockDim.x)
        g_cnt[i] = 0;
}
__device__ __forceinline__ int edge_dst(const int* __restrict__ ei, int e) {
    return (e < N_EDGES) ? ei[N_EDGES + e] : (e - N_EDGES);
}
__device__ __forceinline__ int edge_src(const int* __restrict__ ei, int e) {
    return (e < N_EDGES) ? ei[e] : (e - N_EDGES);
}
__global__ void hist_k(const int* __restrict__ ei) {
    int e = blockIdx.x * blockDim.x + threadIdx.x;
    if (e < N_ET) atomicAdd(&g_cnt[edge_dst(ei, e)], 1);
}

// ---------------- three-phase multi-block exclusive scan ----------------
__global__ void scan1_k() {               // per-block reduction
    __shared__ int sh[256];
    int i = blockIdx.x * 256 + threadIdx.x;
    int v = (i < N_NODES) ? g_cnt[i] : 0;
    sh[threadIdx.x] = v;
    __syncthreads();
    #pragma unroll
    for (int d = 128; d > 0; d >>= 1) {
        if (threadIdx.x < d) sh[threadIdx.x] += sh[threadIdx.x + d];
        __syncthreads();
    }
    if (threadIdx.x == 0) g_bsum[blockIdx.x] = sh[0];
}
__global__ void scan2_k() {               // scan the 196 block sums
    __shared__ int sh[256];
    int t = threadIdx.x;
    int v = (t < NB_SCAN) ? g_bsum[t] : 0;
    sh[t] = v;
    __syncthreads();
    #pragma unroll
    for (int d = 1; d < 256; d <<= 1) {
        int u = (t >= d) ? sh[t - d] : 0;
        __syncthreads();
        sh[t] += u;
        __syncthreads();
    }
    if (t < NB_SCAN) g_bsum[t] = sh[t] - v;   // exclusive
    if (t == 0) g_start[N_NODES] = N_ET;
}
__global__ void scan3_k() {               // per-block exclusive scan + offset
    __shared__ int sh[256];
    int t = threadIdx.x;
    int i = blockIdx.x * 256 + t;
    int v = (i < N_NODES) ? g_cnt[i] : 0;
    sh[t] = v;
    __syncthreads();
    #pragma unroll
    for (int d = 1; d < 256; d <<= 1) {
        int u = (t >= d) ? sh[t - d] : 0;
        __syncthreads();
        sh[t] += u;
        __syncthreads();
    }
    int ex = sh[t] - v + g_bsum[blockIdx.x];
    if (i < N_NODES) { g_start[i] = ex; g_cursor[i] = ex; }
}

__global__ void scatter_k(const int* __restrict__ ei) {
    int e = blockIdx.x * blockDim.x + threadIdx.x;
    if (e < N_ET) {
        int d = edge_dst(ei, e);
        int s = edge_src(ei, e);
        int pos = atomicAdd(&g_cursor[d], 1);
        g_sorted[pos] = s;
    }
}

// ---------------- weight -> bf16 hi/lo images, [n][k] row-major ----------
__global__ void bimg_k(const float* __restrict__ W1l, const float* __restrict__ W1r,
                       const float* __restrict__ W2l, const float* __restrict__ W2r) {
    int t = blockIdx.x * blockDim.x + threadIdx.x;
    if (t < 256 * 128) {                    // layer 1
        int n = t >> 7, k = t & 127;
        float v = (n < 128) ? W1l[k * 128 + n] : W1r[k * 128 + (n - 128)];
        __nv_bfloat16 h = __float2bfloat16_rn(v);
        g_B1hi[n * 128 + k] = h;
        g_B1lo[n * 128 + k] = __float2bfloat16_rn(v - __bfloat162float(h));
    } else if (t < 256 * 128 + 128 * 128) { // layer 2
        int t2 = t - 256 * 128;
        int n = t2 >> 7, k = t2 & 127;
        float v = (n < 64) ? W2l[k * 64 + n] : W2r[k * 64 + (n - 64)];
        __nv_bfloat16 h = __float2bfloat16_rn(v);
        g_B2hi[n * 128 + k] = h;
        g_B2lo[n * 128 + k] = __float2bfloat16_rn(v - __bfloat162float(h));
    }
}

// ---------------- mma.sync helpers (sm_80 baseline, works on sm_103) -----
__device__ __forceinline__ void ldsm_x4(uint32_t* r, uint32_t addr) {
    asm volatile("ldmatrix.sync.aligned.m8n8.x4.shared.b16 {%0,%1,%2,%3}, [%4];"
        : "=r"(r[0]), "=r"(r[1]), "=r"(r[2]), "=r"(r[3]) : "r"(addr));
}
__device__ __forceinline__ void mma_bf16(float* d, const uint32_t* a,
                                         uint32_t b0, uint32_t b1) {
    asm volatile("mma.sync.aligned.m16n8k16.row.col.f32.bf16.bf16.f32 "
        "{%0,%1,%2,%3}, {%4,%5,%6,%7}, {%8,%9}, {%0,%1,%2,%3};"
        : "+f"(d[0]), "+f"(d[1]), "+f"(d[2]), "+f"(d[3])
        : "r"(a[0]), "r"(a[1]), "r"(a[2]), "r"(a[3]), "r"(b0), "r"(b1));
}

// ---------------- HMMA split-bf16 dual GEMM (2 blocks/SM) ----------------
// D[128, NOUT] = Ahi@Bhi + Ahi@Blo + Alo@Bhi, fp32 accum.
// A (full K=128, hi/lo) resident in smem once; B staged in half-K chunks
// (128 rows x 64 bf16, 144-B stride) -> 106.5 KB total, 2 blocks/SM.
template <int NOUT, int HALF, bool CONVERT>
__global__ void __launch_bounds__(256, 2)
gemm_tc_k(const float* __restrict__ xf,
          const __nv_bfloat16* __restrict__ ahi_g,
          const __nv_bfloat16* __restrict__ alo_g,
          const __nv_bfloat16* __restrict__ bhi_img,
          const __nv_bfloat16* __restrict__ blo_img,
          float* __restrict__ xl, float* __restrict__ xr) {
    extern __shared__ char smem[];
    constexpr int STRA = 272;                 // A row: 136 bf16
    constexpr int STRH = 144;                 // B row: 72 bf16 (64 data + pad)
    constexpr int A_HI = 0;
    constexpr int A_LO = A_HI + 128 * STRA;   // 34816
    constexpr int B_HI = A_LO + 128 * STRA;   // 69632
    constexpr int B_LO = B_HI + 128 * STRH;   // 88064  (total 106496)
    constexpr int NPASS = NOUT / 128;
    const int tid = threadIdx.x, wid = tid >> 5, lane = tid & 31;
    const int row0 = blockIdx.x * 128;
    uint32_t sb;
    asm("{ .reg .u64 t; cvta.to.shared.u64 t, %1; cvt.u32.u64 %0, t; }"
        : "=r"(sb) : "l"(smem));

    // ---- A tile (once, full K) ----
    if (CONVERT) {
        const float4* xt = (const float4*)(xf + (size_t)row0 * 128);
        for (int idx = tid; idx < 4096; idx += 256) {
            int r = idx >> 5, k4 = idx & 31, c0 = k4 * 4;
            float4 v = make_float4(0.f, 0.f, 0.f, 0.f);
            if (row0 + r < N_NODES) v = xt[idx];
            __nv_bfloat16 h0 = __float2bfloat16_rn(v.x);
            __nv_bfloat16 h1 = __float2bfloat16_rn(v.y);
            __nv_bfloat16 h2 = __float2bfloat16_rn(v.z);
            __nv_bfloat16 h3 = __float2bfloat16_rn(v.w);
            ushort hh[4] = { __bfloat16_as_ushort(h0), __bfloat16_as_ushort(h1),
                             __bfloat16_as_ushort(h2), __bfloat16_as_ushort(h3) };
            ushort ll[4] = {
                __bfloat16_as_ushort(__float2bfloat16_rn(v.x - __bfloat162float(h0))),
                __bfloat16_as_ushort(__float2bfloat16_rn(v.y - __bfloat162float(h1))),
                __bfloat16_as_ushort(__float2bfloat16_rn(v.z - __bfloat162float(h2))),
                __bfloat16_as_ushort(__float2bfloat16_rn(v.w - __bfloat162float(h3))) };
            *(uint2*)(smem + A_HI + r * STRA + c0 * 2) = *(const uint2*)hh;
            *(uint2*)(smem + A_LO + r * STRA + c0 * 2) = *(const uint2*)ll;
        }
    } else {
        const uint4* s1 = (const uint4*)ahi_g;
        const uint4* s2 = (const uint4*)alo_g;
        for (int idx = tid; idx < 2048; idx += 256) {
            int r = idx >> 4, seg = idx & 15;
            uint4 v1 = make_uint4(0u, 0u, 0u, 0u), v2 = v1;
            if (row0 + r < N_NODES) {
                v1 = s1[(size_t)(row0 + r) * 16 + seg];
                v2 = s2[(size_t)(row0 + r) * 16 + seg];
            }
            *(uint4*)(smem + A_HI + r * STRA + seg * 16) = v1;
            *(uint4*)(smem + A_LO + r * STRA + seg * 16) = v2;
        }
    }

    // warp-tile addressing (fixed across passes)
    const int m0 = wid * 16;
    uint32_t aRow = m0 + (lane & 15);
    uint32_t aCol = (lane >> 4) * 16;              // bytes
    uint32_t aAddrH = sb + A_HI + aRow * STRA + aCol;
    uint32_t aAddrL = sb + A_LO + aRow * STRA + aCol;
    int g = lane >> 3;
    uint32_t bRow = (lane & 7) + ((g & 2) << 2);   // +8 for g>=2
    uint32_t bCol = (g & 1) * 16;                  // bytes
    uint32_t bAddrH = sb + B_HI + bRow * STRH + bCol;
    uint32_t bAddrL = sb + B_LO + bRow * STRH + bCol;
    const int rq = lane >> 2;
    const int cq = (lane & 3) * 2;
    const int r0g = row0 + m0 + rq;
    const int r1g = r0g + 8;

    const uint4* bs1 = (const uint4*)bhi_img;
    const uint4* bs2 = (const uint4*)blo_img;

    #pragma unroll 1
    for (int nh = 0; nh < NPASS; nh++) {
        float acc[16][4];
        #pragma unroll
        for (int i = 0; i < 16; i++)
            #pragma unroll
            for (int j = 0; j < 4; j++) acc[i][j] = 0.f;

        #pragma unroll 1
        for (int kh = 0; kh < 2; kh++) {
            __syncthreads();              // prior pass done reading B (covers A too)
            // B half-K chunk: rows nh*128..+128, k in [kh*64, kh*64+64)
            for (int i = tid; i < 128 * 8; i += 256) {
                int r = i >> 3, seg = i & 7;
                *(uint4*)(smem + B_HI + r * STRH + seg * 16) =
                    bs1[(nh * 128 + r) * 16 + kh * 8 + seg];
                *(uint4*)(smem + B_LO + r * STRH + seg * 16) =
                    bs2[(nh * 128 + r) * 16 + kh * 8 + seg];
            }
            __syncthreads();

            #pragma unroll
            for (int ks = 0; ks < 4; ks++) {
                uint32_t ka = kh * 128 + ks * 32;  // A byte offset
                uint32_t kb = ks * 32;             // B byte offset
                uint32_t ah[4], al[4];
                ldsm_x4(ah, aAddrH + ka);
                ldsm_x4(al, aAddrL + ka);
                #pragma unroll
                for (int nt2 = 0; nt2 < 8; nt2++) {
                    uint32_t off = nt2 * (16 * STRH) + kb;
                    uint32_t bh[4], bl[4];
                    ldsm_x4(bh, bAddrH + off);
                    ldsm_x4(bl, bAddrL + off);
                    mma_bf16(acc[nt2 * 2],     ah, bh[0], bh[1]);
                    mma_bf16(acc[nt2 * 2],     ah, bl[0], bl[1]);
                    mma_bf16(acc[nt2 * 2],     al, bh[0], bh[1]);
                    mma_bf16(acc[nt2 * 2 + 1], ah, bh[2], bh[3]);
                    mma_bf16(acc[nt2 * 2 + 1], ah, bl[2], bl[3]);
                    mma_bf16(acc[nt2 * 2 + 1], al, bh[2], bh[3]);
                }
            }
        }

        // ---- epilogue: direct float2 stores (full 32B sectors) ----
        #pragma unroll
        for (int nt = 0; nt < 16; nt++) {
            int gc = nh * 128 + nt * 8 + cq;
            float2 v0 = make_float2(acc[nt][0], acc[nt][1]);
            float2 v1 = make_float2(acc[nt][2], acc[nt][3]);
            if (gc < HALF) {
                if (r0g < N_NODES) *(float2*)&xl[(size_t)r0g * HALF + gc] = v0;
                if (r1g < N_NODES) *(float2*)&xl[(size_t)r1g * HALF + gc] = v1;
            } else {
                int g2 = gc - HALF;
                if (r0g < N_NODES) *(float2*)&xr[(size_t)r0g * HALF + g2] = v0;
                if (r1g < N_NODES) *(float2*)&xr[(size_t)r1g * HALF + g2] = v1;
            }
        }
    }
}

// ---------------- fused GATv2 softmax + aggregation (one warp per node) --
// Single pass, no max-subtraction (scores O(5), fp32-exp safe).
// MODE 0: fp32 out + bias. MODE 1: bias + ELU, output split bf16 hi/lo.
template <int H, int C, int MODE>
__global__ void agg_k(const float* __restrict__ xl, const float* __restrict__ xr,
                      const float* __restrict__ att, const float* __restrict__ bias,
                      float* __restrict__ outf,
                      __nv_bfloat16* __restrict__ ohi, __nv_bfloat16* __restrict__ olo) {
    constexpr int HC  = H * C;
    constexpr int VEC = HC / 32;       // 4 (layer1) or 2 (layer2)
    constexpr int LPH = C / VEC;       // lanes per head
    const int lane = threadIdx.x & 31;
    const int d = blockIdx.x * (blockDim.x >> 5) + (threadIdx.x >> 5);
    if (d >= N_NODES) return;
    const int base = lane * VEC;

    float xrv[VEC], attv[VEC];
    #pragma unroll
    for (int v = 0; v < VEC; v++) {
        xrv[v]  = xr[(size_t)d * HC + base + v];
        attv[v] = att[base + v];
    }
    const int s0 = g_start[d], s1 = g_start[d + 1];

    float acc[VEC];
    #pragma unroll
    for (int v = 0; v < VEC; v++) acc[v] = 0.f;
    float den = 0.f;

    float xn[VEC];
    if (s0 < s1) {
        const float* xp = xl + (size_t)g_sorted[s0] * HC + base;
        if (VEC == 4) {
            float4 t = *(const float4*)xp;
            xn[0] = t.x; xn[1] = t.y; xn[2] = t.z; xn[3] = t.w;
        } else {
            float2 t = *(const float2*)xp;
            xn[0] = t.x; xn[1] = t.y;
        }
    }
    for (int j = s0; j < s1; j++) {
        float xv[VEC];
        #pragma unroll
        for (int v = 0; v < VEC; v++) xv[v] = xn[v];
        if (j + 1 < s1) {
            const float* xp = xl + (size_t)g_sorted[j + 1] * HC + base;
            if (VEC == 4) {
                float4 t = *(const float4*)xp;
                xn[0] = t.x; xn[1] = t.y; xn[2] = t.z; xn[3] = t.w;
            } else {
                float2 t = *(const float2*)xp;
                xn[0] = t.x; xn[1] = t.y;
            }
        }
        float s = 0.f;
        #pragma unroll
        for (int v = 0; v < VEC; v++) {
            float m = xv[v] + xrv[v];
            m = (m > 0.f) ? m : 0.2f * m;      // leaky_relu
            s = fmaf(m, attv[v], s);
        }
        #pragma unroll
        for (int w = LPH >> 1; w > 0; w >>= 1)
            s += __shfl_xor_sync(0xffffffffu, s, w);
        float p = __expf(s);
        den += p;
        #pragma unroll
        for (int v = 0; v < VEC; v++) acc[v] = fmaf(p, xv[v], acc[v]);
    }

    const float inv = 1.0f / den;       // self-loop guarantees den > 0
    if (MODE == 0) {
        #pragma unroll
        for (int v = 0; v < VEC; v++)
            outf[(size_t)d * HC + base + v] = acc[v] * inv + bias[base + v];
    } else {
        ushort hh[VEC], ll[VEC];
        #pragma unroll
        for (int v = 0; v < VEC; v++) {
            float r = acc[v] * inv + bias[base + v];
            r = (r > 0.f) ? r : (__expf(r) - 1.0f);   // ELU
            __nv_bfloat16 hb = __float2bfloat16_rn(r);
            hh[v] = __bfloat16_as_ushort(hb);
            ll[v] = __bfloat16_as_ushort(__float2bfloat16_rn(r - __bfloat162float(hb)));
        }
        size_t o = ((size_t)d * HC + base) >> 2;      // VEC==4: uint2 granules
        ((uint2*)ohi)[o] = *(const uint2*)hh;
        ((uint2*)olo)[o] = *(const uint2*)ll;
    }
}

// ---------------- launch ----------------
extern "C" void kernel_launch(void* const* d_in, const int* in_sizes, int n_in,
                              void* d_out, int out_size) {
    const float* x    = (const float*)d_in[0];
    const int*   ei   = (const int*)  d_in[1];
    const float* W1l  = (const float*)d_in[2];
    const float* W1r  = (const float*)d_in[3];
    const float* att1 = (const float*)d_in[4];
    const float* b1   = (const float*)d_in[5];
    const float* W2l  = (const float*)d_in[6];
    const float* W2r  = (const float*)d_in[7];
    const float* att2 = (const float*)d_in[8];
    const float* b2   = (const float*)d_in[9];
    float* out = (float*)d_out;

    float *xl1, *xr1, *xl2, *xr2;
    __nv_bfloat16 *hhi, *hlo, *b1hi, *b1lo, *b2hi, *b2lo;
    cudaGetSymbolAddress((void**)&xl1, g_xl1);
    cudaGetSymbolAddress((void**)&xr1, g_xr1);
    cudaGetSymbolAddress((void**)&hhi, g_hhi);
    cudaGetSymbolAddress((void**)&hlo, g_hlo);
    cudaGetSymbolAddress((void**)&xl2, g_xl2);
    cudaGetSymbolAddress((void**)&xr2, g_xr2);
    cudaGetSymbolAddress((void**)&b1hi, g_B1hi);
    cudaGetSymbolAddress((void**)&b1lo, g_B1lo);
    cudaGetSymbolAddress((void**)&b2hi, g_B2hi);
    cudaGetSymbolAddress((void**)&b2lo, g_B2lo);

    constexpr int SMEMB = 2 * 128 * 272 + 2 * 128 * 144;   // 106496
    cudaFuncSetAttribute(gemm_tc_k<256, 128, true>,
                         cudaFuncAttributeMaxDynamicSharedMemorySize, SMEMB);
    cudaFuncSetAttribute(gemm_tc_k<128, 64, false>,
                         cudaFuncAttributeMaxDynamicSharedMemorySize, SMEMB);

    const int ETB = (N_ET + 255) / 256;
    const int GT  = (N_NODES + 127) / 128;   // 391 gemm tiles

    // NOTE: gemm1 placed 4th — the ncu capture slot — for visibility.
    zero_cnt_k<<<148, 256>>>();
    hist_k<<<ETB, 256>>>(ei);
    bimg_k<<<192, 256>>>(W1l, W1r, W2l, W2r);
    gemm_tc_k<256, 128, true><<<GT, 256, SMEMB>>>(x, nullptr, nullptr,
                                                  b1hi, b1lo, xl1, xr1);
    scan1_k<<<NB_SCAN, 256>>>();
    scan2_k<<<1, 256>>>();
    scan3_k<<<NB_SCAN, 256>>>();
    scatter_k<<<ETB, 256>>>(ei);

    agg_k<4, 32, 1><<<(N_NODES + 7) / 8, 256>>>(xl1, xr1, att1, b1,
                                                nullptr, hhi, hlo);
    gemm_tc_k<128, 64, false><<<GT, 256, SMEMB>>>(nullptr, hhi, hlo,
                                                  b2hi, b2lo, xl2, xr2);
    agg_k<1, 64, 0><<<(N_NODES + 7) / 8, 256>>>(xl2, xr2, att2, b2,
                                                out, nullptr, nullptr);
}

// round 12
// speedup vs baseline: 1.2174x; 1.0139x over previous
#include <cuda_runtime.h>
#include <cuda_bf16.h>
#include <math.h>
#include <stdint.h>

#define N_NODES 50000
#define N_EDGES 500000
#define N_ET    (N_NODES + N_EDGES)   // 550000 edges incl. self-loops
#define NB_SCAN ((N_NODES + 255) / 256)   // 196 scan blocks

// ---------------- static scratch (no allocations allowed) ----------------
__device__ float g_xl1[N_NODES * 128];
__device__ float g_xr1[N_NODES * 128];
__device__ __nv_bfloat16 g_hhi[N_NODES * 128];
__device__ __nv_bfloat16 g_hlo[N_NODES * 128];
__device__ float g_xl2[N_NODES * 64];
__device__ float g_xr2[N_NODES * 64];
__device__ int   g_cnt   [N_NODES];
__device__ int   g_start [N_NODES + 1];
__device__ int   g_cursor[N_NODES];
__device__ int   g_sorted[N_ET];
__device__ int   g_bsum  [256];
// bf16 weight images, plain [n][k] row-major (ldmatrix-native for B operand)
__device__ __nv_bfloat16 g_B1hi[256 * 128];
__device__ __nv_bfloat16 g_B1lo[256 * 128];
__device__ __nv_bfloat16 g_B2hi[128 * 128];
__device__ __nv_bfloat16 g_B2lo[128 * 128];

// ---------------- counting sort of edges by destination ----------------
__global__ void zero_cnt_k() {
    for (int i = blockIdx.x * blockDim.x + threadIdx.x; i < N_NODES;
         i += gridDim.x * blockDim.x)
        g_cnt[i] = 0;
}
__device__ __forceinline__ int edge_dst(const int* __restrict__ ei, int e) {
    return (e < N_EDGES) ? ei[N_EDGES + e] : (e - N_EDGES);
}
__device__ __forceinline__ int edge_src(const int* __restrict__ ei, int e) {
    return (e < N_EDGES) ? ei[e] : (e - N_EDGES);
}
__global__ void hist_k(const int* __restrict__ ei) {
    int e = blockIdx.x * blockDim.x + threadIdx.x;
    if (e < N_ET) atomicAdd(&g_cnt[edge_dst(ei, e)], 1);
}

// ---------------- three-phase multi-block exclusive scan ----------------
__global__ void scan1_k() {               // per-block reduction
    __shared__ int sh[256];
    int i = blockIdx.x * 256 + threadIdx.x;
    int v = (i < N_NODES) ? g_cnt[i] : 0;
    sh[threadIdx.x] = v;
    __syncthreads();
    #pragma unroll
    for (int d = 128; d > 0; d >>= 1) {
        if (threadIdx.x < d) sh[threadIdx.x] += sh[threadIdx.x + d];
        __syncthreads();
    }
    if (threadIdx.x == 0) g_bsum[blockIdx.x] = sh[0];
}
__global__ void scan2_k() {               // scan the 196 block sums
    __shared__ int sh[256];
    int t = threadIdx.x;
    int v = (t < NB_SCAN) ? g_bsum[t] : 0;
    sh[t] = v;
    __syncthreads();
    #pragma unroll
    for (int d = 1; d < 256; d <<= 1) {
        int u = (t >= d) ? sh[t - d] : 0;
        __syncthreads();
        sh[t] += u;
        __syncthreads();
    }
    if (t < NB_SCAN) g_bsum[t] = sh[t] - v;   // exclusive
    if (t == 0) g_start[N_NODES] = N_ET;
}
__global__ void scan3_k() {               // per-block exclusive scan + offset
    __shared__ int sh[256];
    int t = threadIdx.x;
    int i = blockIdx.x * 256 + t;
    int v = (i < N_NODES) ? g_cnt[i] : 0;
    sh[t] = v;
    __syncthreads();
    #pragma unroll
    for (int d = 1; d < 256; d <<= 1) {
        int u = (t >= d) ? sh[t - d] : 0;
        __syncthreads();
        sh[t] += u;
        __syncthreads();
    }
    int ex = sh[t] - v + g_bsum[blockIdx.x];
    if (i < N_NODES) { g_start[i] = ex; g_cursor[i] = ex; }
}

__global__ void scatter_k(const int* __restrict__ ei) {
    int e = blockIdx.x * blockDim.x + threadIdx.x;
    if (e < N_ET) {
        int d = edge_dst(ei, e);
        int s = edge_src(ei, e);
        int pos = atomicAdd(&g_cursor[d], 1);
        g_sorted[pos] = s;
    }
}

// ---------------- weight -> bf16 hi/lo images, [n][k] row-major ----------
__global__ void bimg_k(const float* __restrict__ W1l, const float* __restrict__ W1r,
                       const float* __restrict__ W2l, const float* __restrict__ W2r) {
    int t = blockIdx.x * blockDim.x + threadIdx.x;
    if (t < 256 * 128) {                    // layer 1
        int n = t >> 7, k = t & 127;
        float v = (n < 128) ? W1l[k * 128 + n] : W1r[k * 128 + (n - 128)];
        __nv_bfloat16 h = __float2bfloat16_rn(v);
        g_B1hi[n * 128 + k] = h;
        g_B1lo[n * 128 + k] = __float2bfloat16_rn(v - __bfloat162float(h));
    } else if (t < 256 * 128 + 128 * 128) { // layer 2
        int t2 = t - 256 * 128;
        int n = t2 >> 7, k = t2 & 127;
        float v = (n < 64) ? W2l[k * 64 + n] : W2r[k * 64 + (n - 64)];
        __nv_bfloat16 h = __float2bfloat16_rn(v);
        g_B2hi[n * 128 + k] = h;
        g_B2lo[n * 128 + k] = __float2bfloat16_rn(v - __bfloat162float(h));
    }
}

// ---------------- mma.sync helpers (sm_80 baseline, works on sm_103) -----
__device__ __forceinline__ void ldsm_x4(uint32_t* r, uint32_t addr) {
    asm volatile("ldmatrix.sync.aligned.m8n8.x4.shared.b16 {%0,%1,%2,%3}, [%4];"
        : "=r"(r[0]), "=r"(r[1]), "=r"(r[2]), "=r"(r[3]) : "r"(addr));
}
__device__ __forceinline__ void mma_bf16(float* d, const uint32_t* a,
                                         uint32_t b0, uint32_t b1) {
    asm volatile("mma.sync.aligned.m16n8k16.row.col.f32.bf16.bf16.f32 "
        "{%0,%1,%2,%3}, {%4,%5,%6,%7}, {%8,%9}, {%0,%1,%2,%3};"
        : "+f"(d[0]), "+f"(d[1]), "+f"(d[2]), "+f"(d[3])
        : "r"(a[0]), "r"(a[1]), "r"(a[2]), "r"(a[3]), "r"(b0), "r"(b1));
}

// ---------------- HMMA split-bf16 dual GEMM (2 blocks/SM) ----------------
// D[128, NOUT] = Ahi@Bhi + Ahi@Blo + Alo@Bhi, fp32 accum.
// Warp tile 32x64 (8 warps = 4 row-groups x 2 col-groups): per k-step
// 4 A-ldsm + 8 B-ldsm (B duplication 4x, was 8x with 16x128 tiles).
// A (full K=128, hi/lo) resident; B staged in half-K chunks. 106.5 KB smem.
template <int NOUT, int HALF, bool CONVERT>
__global__ void __launch_bounds__(256, 2)
gemm_tc_k(const float* __restrict__ xf,
          const __nv_bfloat16* __restrict__ ahi_g,
          const __nv_bfloat16* __restrict__ alo_g,
          const __nv_bfloat16* __restrict__ bhi_img,
          const __nv_bfloat16* __restrict__ blo_img,
          float* __restrict__ xl, float* __restrict__ xr) {
    extern __shared__ char smem[];
    constexpr int STRA = 272;                 // A row: 136 bf16
    constexpr int STRH = 144;                 // B row: 72 bf16 (64 data + pad)
    constexpr int A_HI = 0;
    constexpr int A_LO = A_HI + 128 * STRA;   // 34816
    constexpr int B_HI = A_LO + 128 * STRA;   // 69632
    constexpr int B_LO = B_HI + 128 * STRH;   // 88064  (total 106496)
    constexpr int NPASS = NOUT / 128;
    const int tid = threadIdx.x, wid = tid >> 5, lane = tid & 31;
    const int row0 = blockIdx.x * 128;
    uint32_t sb;
    asm("{ .reg .u64 t; cvta.to.shared.u64 t, %1; cvt.u32.u64 %0, t; }"
        : "=r"(sb) : "l"(smem));

    // ---- A tile (once, full K) ----
    if (CONVERT) {
        const float4* xt = (const float4*)(xf + (size_t)row0 * 128);
        for (int idx = tid; idx < 4096; idx += 256) {
            int r = idx >> 5, k4 = idx & 31, c0 = k4 * 4;
            float4 v = make_float4(0.f, 0.f, 0.f, 0.f);
            if (row0 + r < N_NODES) v = xt[idx];
            __nv_bfloat16 h0 = __float2bfloat16_rn(v.x);
            __nv_bfloat16 h1 = __float2bfloat16_rn(v.y);
            __nv_bfloat16 h2 = __float2bfloat16_rn(v.z);
            __nv_bfloat16 h3 = __float2bfloat16_rn(v.w);
            ushort hh[4] = { __bfloat16_as_ushort(h0), __bfloat16_as_ushort(h1),
                             __bfloat16_as_ushort(h2), __bfloat16_as_ushort(h3) };
            ushort ll[4] = {
                __bfloat16_as_ushort(__float2bfloat16_rn(v.x - __bfloat162float(h0))),
                __bfloat16_as_ushort(__float2bfloat16_rn(v.y - __bfloat162float(h1))),
                __bfloat16_as_ushort(__float2bfloat16_rn(v.z - __bfloat162float(h2))),
                __bfloat16_as_ushort(__float2bfloat16_rn(v.w - __bfloat162float(h3))) };
            *(uint2*)(smem + A_HI + r * STRA + c0 * 2) = *(const uint2*)hh;
            *(uint2*)(smem + A_LO + r * STRA + c0 * 2) = *(const uint2*)ll;
        }
    } else {
        const uint4* s1 = (const uint4*)ahi_g;
        const uint4* s2 = (const uint4*)alo_g;
        for (int idx = tid; idx < 2048; idx += 256) {
            int r = idx >> 4, seg = idx & 15;
            uint4 v1 = make_uint4(0u, 0u, 0u, 0u), v2 = v1;
            if (row0 + r < N_NODES) {
                v1 = s1[(size_t)(row0 + r) * 16 + seg];
                v2 = s2[(size_t)(row0 + r) * 16 + seg];
            }
            *(uint4*)(smem + A_HI + r * STRA + seg * 16) = v1;
            *(uint4*)(smem + A_LO + r * STRA + seg * 16) = v2;
        }
    }

    // warp-tile addressing: wr = row group (32 rows), wc = col group (64 cols)
    const int wr = wid & 3, wc = wid >> 2;
    const int m0 = wr * 32;
    const int n0 = wc * 64;
    uint32_t aRow = m0 + (lane & 15);
    uint32_t aCol = (lane >> 4) * 16;              // bytes
    uint32_t aAddrH = sb + A_HI + aRow * STRA + aCol;   // rows m0..m0+15
    uint32_t aAddrL = sb + A_LO + aRow * STRA + aCol;
    constexpr uint32_t A16 = 16;                   // +16 rows offset (xSTRA)
    int g = lane >> 3;
    uint32_t bRow = n0 + (lane & 7) + ((g & 2) << 2);
    uint32_t bCol = (g & 1) * 16;                  // bytes
    uint32_t bAddrH = sb + B_HI + bRow * STRH + bCol;
    uint32_t bAddrL = sb + B_LO + bRow * STRH + bCol;
    const int rq = lane >> 2;
    const int cq = (lane & 3) * 2;
    const int r0g = row0 + m0 + rq;

    const uint4* bs1 = (const uint4*)bhi_img;
    const uint4* bs2 = (const uint4*)blo_img;

    #pragma unroll 1
    for (int nh = 0; nh < NPASS; nh++) {
        float acc[16][4];     // [sub*8 + n8tile][quad] ; sub = row subtile
        #pragma unroll
        for (int i = 0; i < 16; i++)
            #pragma unroll
            for (int j = 0; j < 4; j++) acc[i][j] = 0.f;

        #pragma unroll 1
        for (int kh = 0; kh < 2; kh++) {
            __syncthreads();              // prior pass done reading B
            // B half-K chunk: rows nh*128..+128, k in [kh*64, kh*64+64)
            for (int i = tid; i < 128 * 8; i += 256) {
                int r = i >> 3, seg = i & 7;
                *(uint4*)(smem + B_HI + r * STRH + seg * 16) =
                    bs1[(nh * 128 + r) * 16 + kh * 8 + seg];
                *(uint4*)(smem + B_LO + r * STRH + seg * 16) =
                    bs2[(nh * 128 + r) * 16 + kh * 8 + seg];
            }
            __syncthreads();

            #pragma unroll
            for (int ks = 0; ks < 4; ks++) {
                uint32_t ka = kh * 128 + ks * 32;  // A byte offset
                uint32_t kb = ks * 32;             // B byte offset
                uint32_t ah0[4], ah1[4], al0[4], al1[4];
                ldsm_x4(ah0, aAddrH + ka);
                ldsm_x4(ah1, aAddrH + A16 * STRA + ka);
                ldsm_x4(al0, aAddrL + ka);
                ldsm_x4(al1, aAddrL + A16 * STRA + ka);
                #pragma unroll
                for (int nt4 = 0; nt4 < 4; nt4++) {
                    uint32_t off = nt4 * (16 * STRH) + kb;
                    uint32_t bh[4], bl[4];
                    ldsm_x4(bh, bAddrH + off);
                    ldsm_x4(bl, bAddrL + off);
                    int i0 = nt4 * 2, i1 = nt4 * 2 + 1;
                    mma_bf16(acc[i0],     ah0, bh[0], bh[1]);
                    mma_bf16(acc[i0],     ah0, bl[0], bl[1]);
                    mma_bf16(acc[i0],     al0, bh[0], bh[1]);
                    mma_bf16(acc[i1],     ah0, bh[2], bh[3]);
                    mma_bf16(acc[i1],     ah0, bl[2], bl[3]);
                    mma_bf16(acc[i1],     al0, bh[2], bh[3]);
                    mma_bf16(acc[8 + i0], ah1, bh[0], bh[1]);
                    mma_bf16(acc[8 + i0], ah1, bl[0], bl[1]);
                    mma_bf16(acc[8 + i0], al1, bh[0], bh[1]);
                    mma_bf16(acc[8 + i1], ah1, bh[2], bh[3]);
                    mma_bf16(acc[8 + i1], ah1, bl[2], bl[3]);
                    mma_bf16(acc[8 + i1], al1, bh[2], bh[3]);
                }
            }
        }

        // ---- epilogue: direct float2 stores (full 32B sectors) ----
        #pragma unroll
        for (int sub = 0; sub < 2; sub++) {
            int ra = r0g + sub * 16;
            int rb = ra + 8;
            #pragma unroll
            for (int nt = 0; nt < 8; nt++) {
                int gc = nh * 128 + n0 + nt * 8 + cq;
                const float* a = acc[sub * 8 + nt];
                float2 v0 = make_float2(a[0], a[1]);
                float2 v1 = make_float2(a[2], a[3]);
                if (gc < HALF) {
                    if (ra < N_NODES) *(float2*)&xl[(size_t)ra * HALF + gc] = v0;
                    if (rb < N_NODES) *(float2*)&xl[(size_t)rb * HALF + gc] = v1;
                } else {
                    int g2 = gc - HALF;
                    if (ra < N_NODES) *(float2*)&xr[(size_t)ra * HALF + g2] = v0;
                    if (rb < N_NODES) *(float2*)&xr[(size_t)rb * HALF + g2] = v1;
                }
            }
        }
    }
}

// ---------------- fused GATv2 softmax + aggregation (one warp per node) --
// Single pass, no max-subtraction (scores O(5), fp32-exp safe).
// MODE 0: fp32 out + bias. MODE 1: bias + ELU, output split bf16 hi/lo.
template <int H, int C, int MODE>
__global__ void agg_k(const float* __restrict__ xl, const float* __restrict__ xr,
                      const float* __restrict__ att, const float* __restrict__ bias,
                      float* __restrict__ outf,
                      __nv_bfloat16* __restrict__ ohi, __nv_bfloat16* __restrict__ olo) {
    constexpr int HC  = H * C;
    constexpr int VEC = HC / 32;       // 4 (layer1) or 2 (layer2)
    constexpr int LPH = C / VEC;       // lanes per head
    const int lane = threadIdx.x & 31;
    const int d = blockIdx.x * (blockDim.x >> 5) + (threadIdx.x >> 5);
    if (d >= N_NODES) return;
    const int base = lane * VEC;

    float xrv[VEC], attv[VEC];
    #pragma unroll
    for (int v = 0; v < VEC; v++) {
        xrv[v]  = xr[(size_t)d * HC + base + v];
        attv[v] = att[base + v];
    }
    const int s0 = g_start[d], s1 = g_start[d + 1];

    float acc[VEC];
    #pragma unroll
    for (int v = 0; v < VEC; v++) acc[v] = 0.f;
    float den = 0.f;

    float xn[VEC];
    if (s0 < s1) {
        const float* xp = xl + (size_t)g_sorted[s0] * HC + base;
        if (VEC == 4) {
            float4 t = *(const float4*)xp;
            xn[0] = t.x; xn[1] = t.y; xn[2] = t.z; xn[3] = t.w;
        } else {
            float2 t = *(const float2*)xp;
            xn[0] = t.x; xn[1] = t.y;
        }
    }
    for (int j = s0; j < s1; j++) {
        float xv[VEC];
        #pragma unroll
        for (int v = 0; v < VEC; v++) xv[v] = xn[v];
        if (j + 1 < s1) {
            const float* xp = xl + (size_t)g_sorted[j + 1] * HC + base;
            if (VEC == 4) {
                float4 t = *(const float4*)xp;
                xn[0] = t.x; xn[1] = t.y; xn[2] = t.z; xn[3] = t.w;
            } else {
                float2 t = *(const float2*)xp;
                xn[0] = t.x; xn[1] = t.y;
            }
        }
        float s = 0.f;
        #pragma unroll
        for (int v = 0; v < VEC; v++) {
            float m = xv[v] + xrv[v];
            m = (m > 0.f) ? m : 0.2f * m;      // leaky_relu
            s = fmaf(m, attv[v], s);
        }
        #pragma unroll
        for (int w = LPH >> 1; w > 0; w >>= 1)
            s += __shfl_xor_sync(0xffffffffu, s, w);
        float p = __expf(s);
        den += p;
        #pragma unroll
        for (int v = 0; v < VEC; v++) acc[v] = fmaf(p, xv[v], acc[v]);
    }

    const float inv = 1.0f / den;       // self-loop guarantees den > 0
    if (MODE == 0) {
        #pragma unroll
        for (int v = 0; v < VEC; v++)
            outf[(size_t)d * HC + base + v] = acc[v] * inv + bias[base + v];
    } else {
        ushort hh[VEC], ll[VEC];
        #pragma unroll
        for (int v = 0; v < VEC; v++) {
            float r = acc[v] * inv + bias[base + v];
            r = (r > 0.f) ? r : (__expf(r) - 1.0f);   // ELU
            __nv_bfloat16 hb = __float2bfloat16_rn(r);
            hh[v] = __bfloat16_as_ushort(hb);
            ll[v] = __bfloat16_as_ushort(__float2bfloat16_rn(r - __bfloat162float(hb)));
        }
        size_t o = ((size_t)d * HC + base) >> 2;      // VEC==4: uint2 granules
        ((uint2*)ohi)[o] = *(const uint2*)hh;
        ((uint2*)olo)[o] = *(const uint2*)ll;
    }
}

// ---------------- launch ----------------
extern "C" void kernel_launch(void* const* d_in, const int* in_sizes, int n_in,
                              void* d_out, int out_size) {
    const float* x    = (const float*)d_in[0];
    const int*   ei   = (const int*)  d_in[1];
    const float* W1l  = (const float*)d_in[2];
    const float* W1r  = (const float*)d_in[3];
    const float* att1 = (const float*)d_in[4];
    const float* b1   = (const float*)d_in[5];
    const float* W2l  = (const float*)d_in[6];
    const float* W2r  = (const float*)d_in[7];
    const float* att2 = (const float*)d_in[8];
    const float* b2   = (const float*)d_in[9];
    float* out = (float*)d_out;

    float *xl1, *xr1, *xl2, *xr2;
    __nv_bfloat16 *hhi, *hlo, *b1hi, *b1lo, *b2hi, *b2lo;
    cudaGetSymbolAddress((void**)&xl1, g_xl1);
    cudaGetSymbolAddress((void**)&xr1, g_xr1);
    cudaGetSymbolAddress((void**)&hhi, g_hhi);
    cudaGetSymbolAddress((void**)&hlo, g_hlo);
    cudaGetSymbolAddress((void**)&xl2, g_xl2);
    cudaGetSymbolAddress((void**)&xr2, g_xr2);
    cudaGetSymbolAddress((void**)&b1hi, g_B1hi);
    cudaGetSymbolAddress((void**)&b1lo, g_B1lo);
    cudaGetSymbolAddress((void**)&b2hi, g_B2hi);
    cudaGetSymbolAddress((void**)&b2lo, g_B2lo);

    constexpr int SMEMB = 2 * 128 * 272 + 2 * 128 * 144;   // 106496
    cudaFuncSetAttribute(gemm_tc_k<256, 128, true>,
                         cudaFuncAttributeMaxDynamicSharedMemorySize, SMEMB);
    cudaFuncSetAttribute(gemm_tc_k<128, 64, false>,
                         cudaFuncAttributeMaxDynamicSharedMemorySize, SMEMB);

    const int ETB = (N_ET + 255) / 256;
    const int GT  = (N_NODES + 127) / 128;   // 391 gemm tiles

    // NOTE: gemm1 placed 4th — the ncu capture slot — for visibility.
    zero_cnt_k<<<148, 256>>>();
    hist_k<<<ETB, 256>>>(ei);
    bimg_k<<<192, 256>>>(W1l, W1r, W2l, W2r);
    gemm_tc_k<256, 128, true><<<GT, 256, SMEMB>>>(x, nullptr, nullptr,
                                                  b1hi, b1lo, xl1, xr1);
    scan1_k<<<NB_SCAN, 256>>>();
    scan2_k<<<1, 256>>>();
    scan3_k<<<NB_SCAN, 256>>>();
    scatter_k<<<ETB, 256>>>(ei);

    agg_k<4, 32, 1><<<(N_NODES + 7) / 8, 256>>>(xl1, xr1, att1, b1,
                                                nullptr, hhi, hlo);
    gemm_tc_k<128, 64, false><<<GT, 256, SMEMB>>>(nullptr, hhi, hlo,
                                                  b2hi, b2lo, xl2, xr2);
    agg_k<1, 64, 0><<<(N_NODES + 7) / 8, 256>>>(xl2, xr2, att2, b2,
                                                out, nullptr, nullptr);
}

// round 13
// speedup vs baseline: 1.2295x; 1.0099x over previous
#include <cuda_runtime.h>
#include <cuda_bf16.h>
#include <math.h>
#include <stdint.h>

#define N_NODES 50000
#define N_EDGES 500000
#define N_ET    (N_NODES + N_EDGES)   // 550000 edges incl. self-loops
#define NB_SCAN ((N_NODES + 255) / 256)   // 196 scan blocks

// ---------------- static scratch (no allocations allowed) ----------------
__device__ float g_xl1[N_NODES * 128];
__device__ float g_xr1[N_NODES * 128];
__device__ __nv_bfloat16 g_hhi[N_NODES * 128];
__device__ __nv_bfloat16 g_hlo[N_NODES * 128];
__device__ float g_xl2[N_NODES * 64];
__device__ float g_xr2[N_NODES * 64];
__device__ int   g_cnt   [N_NODES];
__device__ int   g_start [N_NODES + 1];
__device__ int   g_cursor[N_NODES];
__device__ int   g_sorted[N_ET];
__device__ int   g_bsum  [256];
// bf16 weight images, plain [n][k] row-major (ldmatrix-native for B operand)
__device__ __nv_bfloat16 g_B1hi[256 * 128];
__device__ __nv_bfloat16 g_B1lo[256 * 128];
__device__ __nv_bfloat16 g_B2hi[128 * 128];
__device__ __nv_bfloat16 g_B2lo[128 * 128];

// ---------------- counting sort of edges by destination ----------------
__global__ void zero_cnt_k() {
    for (int i = blockIdx.x * blockDim.x + threadIdx.x; i < N_NODES;
         i += gridDim.x * blockDim.x)
        g_cnt[i] = 0;
}
__device__ __forceinline__ int edge_dst(const int* __restrict__ ei, int e) {
    return (e < N_EDGES) ? ei[N_EDGES + e] : (e - N_EDGES);
}
__device__ __forceinline__ int edge_src(const int* __restrict__ ei, int e) {
    return (e < N_EDGES) ? ei[e] : (e - N_EDGES);
}
__global__ void hist_k(const int* __restrict__ ei) {
    int e = blockIdx.x * blockDim.x + threadIdx.x;
    if (e < N_ET) atomicAdd(&g_cnt[edge_dst(ei, e)], 1);
}

// ---------------- three-phase multi-block exclusive scan ----------------
__global__ void scan1_k() {               // per-block reduction
    __shared__ int sh[256];
    int i = blockIdx.x * 256 + threadIdx.x;
    int v = (i < N_NODES) ? g_cnt[i] : 0;
    sh[threadIdx.x] = v;
    __syncthreads();
    #pragma unroll
    for (int d = 128; d > 0; d >>= 1) {
        if (threadIdx.x < d) sh[threadIdx.x] += sh[threadIdx.x + d];
        __syncthreads();
    }
    if (threadIdx.x == 0) g_bsum[blockIdx.x] = sh[0];
}
__global__ void scan2_k() {               // scan the 196 block sums
    __shared__ int sh[256];
    int t = threadIdx.x;
    int v = (t < NB_SCAN) ? g_bsum[t] : 0;
    sh[t] = v;
    __syncthreads();
    #pragma unroll
    for (int d = 1; d < 256; d <<= 1) {
        int u = (t >= d) ? sh[t - d] : 0;
        __syncthreads();
        sh[t] += u;
        __syncthreads();
    }
    if (t < NB_SCAN) g_bsum[t] = sh[t] - v;   // exclusive
    if (t == 0) g_start[N_NODES] = N_ET;
}
__global__ void scan3_k() {               // per-block exclusive scan + offset
    __shared__ int sh[256];
    int t = threadIdx.x;
    int i = blockIdx.x * 256 + t;
    int v = (i < N_NODES) ? g_cnt[i] : 0;
    sh[t] = v;
    __syncthreads();
    #pragma unroll
    for (int d = 1; d < 256; d <<= 1) {
        int u = (t >= d) ? sh[t - d] : 0;
        __syncthreads();
        sh[t] += u;
        __syncthreads();
    }
    int ex = sh[t] - v + g_bsum[blockIdx.x];
    if (i < N_NODES) { g_start[i] = ex; g_cursor[i] = ex; }
}

__global__ void scatter_k(const int* __restrict__ ei) {
    int e = blockIdx.x * blockDim.x + threadIdx.x;
    if (e < N_ET) {
        int d = edge_dst(ei, e);
        int s = edge_src(ei, e);
        int pos = atomicAdd(&g_cursor[d], 1);
        g_sorted[pos] = s;
    }
}

// ---------------- weight -> bf16 hi/lo images, [n][k] row-major ----------
__global__ void bimg_k(const float* __restrict__ W1l, const float* __restrict__ W1r,
                       const float* __restrict__ W2l, const float* __restrict__ W2r) {
    int t = blockIdx.x * blockDim.x + threadIdx.x;
    if (t < 256 * 128) {                    // layer 1
        int n = t >> 7, k = t & 127;
        float v = (n < 128) ? W1l[k * 128 + n] : W1r[k * 128 + (n - 128)];
        __nv_bfloat16 h = __float2bfloat16_rn(v);
        g_B1hi[n * 128 + k] = h;
        g_B1lo[n * 128 + k] = __float2bfloat16_rn(v - __bfloat162float(h));
    } else if (t < 256 * 128 + 128 * 128) { // layer 2
        int t2 = t - 256 * 128;
        int n = t2 >> 7, k = t2 & 127;
        float v = (n < 64) ? W2l[k * 64 + n] : W2r[k * 64 + (n - 64)];
        __nv_bfloat16 h = __float2bfloat16_rn(v);
        g_B2hi[n * 128 + k] = h;
        g_B2lo[n * 128 + k] = __float2bfloat16_rn(v - __bfloat162float(h));
    }
}

// ---------------- mma.sync helpers (sm_80 baseline, works on sm_103) -----
__device__ __forceinline__ void ldsm_x4(uint32_t* r, uint32_t addr) {
    asm volatile("ldmatrix.sync.aligned.m8n8.x4.shared.b16 {%0,%1,%2,%3}, [%4];"
        : "=r"(r[0]), "=r"(r[1]), "=r"(r[2]), "=r"(r[3]) : "r"(addr));
}
__device__ __forceinline__ void mma_bf16(float* d, const uint32_t* a,
                                         uint32_t b0, uint32_t b1) {
    asm volatile("mma.sync.aligned.m16n8k16.row.col.f32.bf16.bf16.f32 "
        "{%0,%1,%2,%3}, {%4,%5,%6,%7}, {%8,%9}, {%0,%1,%2,%3};"
        : "+f"(d[0]), "+f"(d[1]), "+f"(d[2]), "+f"(d[3])
        : "r"(a[0]), "r"(a[1]), "r"(a[2]), "r"(a[3]), "r"(b0), "r"(b1));
}

// ---------------- HMMA split-bf16 dual GEMM (2 blocks/SM) ----------------
// D[128, 128] = Ahi@Bhi + Ahi@Blo + Alo@Bhi, fp32 accum. N-half via
// blockIdx.y (fine-grained blocks -> better wave utilization).
// Warp tile 32x64; MMAs issued TERM-MAJOR over 8 independent accumulators
// so dependent-MMA gap (8 issues) exceeds HMMA latency.
template <int HALF, bool CONVERT>
__global__ void __launch_bounds__(256, 2)
gemm_tc_k(const float* __restrict__ xf,
          const __nv_bfloat16* __restrict__ ahi_g,
          const __nv_bfloat16* __restrict__ alo_g,
          const __nv_bfloat16* __restrict__ bhi_img,
          const __nv_bfloat16* __restrict__ blo_img,
          float* __restrict__ xl, float* __restrict__ xr) {
    extern __shared__ char smem[];
    constexpr int STRA = 272;                 // A row: 136 bf16
    constexpr int STRH = 144;                 // B row: 72 bf16 (64 data + pad)
    constexpr int A_HI = 0;
    constexpr int A_LO = A_HI + 128 * STRA;   // 34816
    constexpr int B_HI = A_LO + 128 * STRA;   // 69632
    constexpr int B_LO = B_HI + 128 * STRH;   // 88064  (total 106496)
    const int tid = threadIdx.x, wid = tid >> 5, lane = tid & 31;
    const int row0 = blockIdx.x * 128;
    const int nh   = blockIdx.y;
    uint32_t sb;
    asm("{ .reg .u64 t; cvta.to.shared.u64 t, %1; cvt.u32.u64 %0, t; }"
        : "=r"(sb) : "l"(smem));

    // ---- A tile (full K) ----
    if (CONVERT) {
        const float4* xt = (const float4*)(xf + (size_t)row0 * 128);
        for (int idx = tid; idx < 4096; idx += 256) {
            int r = idx >> 5, k4 = idx & 31, c0 = k4 * 4;
            float4 v = make_float4(0.f, 0.f, 0.f, 0.f);
            if (row0 + r < N_NODES) v = xt[idx];
            __nv_bfloat16 h0 = __float2bfloat16_rn(v.x);
            __nv_bfloat16 h1 = __float2bfloat16_rn(v.y);
            __nv_bfloat16 h2 = __float2bfloat16_rn(v.z);
            __nv_bfloat16 h3 = __float2bfloat16_rn(v.w);
            ushort hh[4] = { __bfloat16_as_ushort(h0), __bfloat16_as_ushort(h1),
                             __bfloat16_as_ushort(h2), __bfloat16_as_ushort(h3) };
            ushort ll[4] = {
                __bfloat16_as_ushort(__float2bfloat16_rn(v.x - __bfloat162float(h0))),
                __bfloat16_as_ushort(__float2bfloat16_rn(v.y - __bfloat162float(h1))),
                __bfloat16_as_ushort(__float2bfloat16_rn(v.z - __bfloat162float(h2))),
                __bfloat16_as_ushort(__float2bfloat16_rn(v.w - __bfloat162float(h3))) };
            *(uint2*)(smem + A_HI + r * STRA + c0 * 2) = *(const uint2*)hh;
            *(uint2*)(smem + A_LO + r * STRA + c0 * 2) = *(const uint2*)ll;
        }
    } else {
        const uint4* s1 = (const uint4*)ahi_g;
        const uint4* s2 = (const uint4*)alo_g;
        for (int idx = tid; idx < 2048; idx += 256) {
            int r = idx >> 4, seg = idx & 15;
            uint4 v1 = make_uint4(0u, 0u, 0u, 0u), v2 = v1;
            if (row0 + r < N_NODES) {
                v1 = s1[(size_t)(row0 + r) * 16 + seg];
                v2 = s2[(size_t)(row0 + r) * 16 + seg];
            }
            *(uint4*)(smem + A_HI + r * STRA + seg * 16) = v1;
            *(uint4*)(smem + A_LO + r * STRA + seg * 16) = v2;
        }
    }

    // warp-tile addressing: wr = row group (32 rows), wc = col group (64 cols)
    const int wr = wid & 3, wc = wid >> 2;
    const int m0 = wr * 32;
    const int n0 = wc * 64;
    uint32_t aRow = m0 + (lane & 15);
    uint32_t aCol = (lane >> 4) * 16;              // bytes
    uint32_t aAddrH = sb + A_HI + aRow * STRA + aCol;
    uint32_t aAddrL = sb + A_LO + aRow * STRA + aCol;
    constexpr uint32_t A16 = 16;                   // +16 rows (xSTRA)
    int g = lane >> 3;
    uint32_t bRow = n0 + (lane & 7) + ((g & 2) << 2);
    uint32_t bCol = (g & 1) * 16;                  // bytes
    uint32_t bAddrH = sb + B_HI + bRow * STRH + bCol;
    uint32_t bAddrL = sb + B_LO + bRow * STRH + bCol;
    const int rq = lane >> 2;
    const int cq = (lane & 3) * 2;
    const int r0g = row0 + m0 + rq;

    const uint4* bs1 = (const uint4*)bhi_img;
    const uint4* bs2 = (const uint4*)blo_img;

    float acc[16][4];     // [sub*8 + n8tile][quad] ; sub = row subtile
    #pragma unroll
    for (int i = 0; i < 16; i++)
        #pragma unroll
        for (int j = 0; j < 4; j++) acc[i][j] = 0.f;

    #pragma unroll 1
    for (int kh = 0; kh < 2; kh++) {
        if (kh) __syncthreads();          // all warps done reading chunk 0
        // B half-K chunk: rows nh*128..+128, k in [kh*64, kh*64+64)
        for (int i = tid; i < 128 * 8; i += 256) {
            int r = i >> 3, seg = i & 7;
            *(uint4*)(smem + B_HI + r * STRH + seg * 16) =
                bs1[(nh * 128 + r) * 16 + kh * 8 + seg];
            *(uint4*)(smem + B_LO + r * STRH + seg * 16) =
                bs2[(nh * 128 + r) * 16 + kh * 8 + seg];
        }
        __syncthreads();

        #pragma unroll
        for (int ks = 0; ks < 4; ks++) {
            uint32_t ka = kh * 128 + ks * 32;  // A byte offset
            uint32_t kb = ks * 32;             // B byte offset
            uint32_t ah0[4], ah1[4], al0[4], al1[4];
            ldsm_x4(ah0, aAddrH + ka);
            ldsm_x4(ah1, aAddrH + A16 * STRA + ka);
            ldsm_x4(al0, aAddrL + ka);
            ldsm_x4(al1, aAddrL + A16 * STRA + ka);
            #pragma unroll
            for (int np = 0; np < 2; np++) {   // pairs of n16 tiles
                uint32_t o0 = (np * 2) * (16 * STRH) + kb;
                uint32_t o1 = (np * 2 + 1) * (16 * STRH) + kb;
                uint32_t bh0[4], bh1[4], bl0[4], bl1[4];
                ldsm_x4(bh0, bAddrH + o0);
                ldsm_x4(bh1, bAddrH + o1);
                ldsm_x4(bl0, bAddrL + o0);
                ldsm_x4(bl1, bAddrL + o1);
                const int a0 = np * 4;
                // term 1: Ahi @ Bhi  (8 independent accs)
                mma_bf16(acc[a0 + 0],     ah0, bh0[0], bh0[1]);
                mma_bf16(acc[a0 + 1],     ah0, bh0[2], bh0[3]);
                mma_bf16(acc[a0 + 2],     ah0, bh1[0], bh1[1]);
                mma_bf16(acc[a0 + 3],     ah0, bh1[2], bh1[3]);
                mma_bf16(acc[8 + a0 + 0], ah1, bh0[0], bh0[1]);
                mma_bf16(acc[8 + a0 + 1], ah1, bh0[2], bh0[3]);
                mma_bf16(acc[8 + a0 + 2], ah1, bh1[0], bh1[1]);
                mma_bf16(acc[8 + a0 + 3], ah1, bh1[2], bh1[3]);
                // term 2: Ahi @ Blo
                mma_bf16(acc[a0 + 0],     ah0, bl0[0], bl0[1]);
                mma_bf16(acc[a0 + 1],     ah0, bl0[2], bl0[3]);
                mma_bf16(acc[a0 + 2],     ah0, bl1[0], bl1[1]);
                mma_bf16(acc[a0 + 3],     ah0, bl1[2], bl1[3]);
                mma_bf16(acc[8 + a0 + 0], ah1, bl0[0], bl0[1]);
                mma_bf16(acc[8 + a0 + 1], ah1, bl0[2], bl0[3]);
                mma_bf16(acc[8 + a0 + 2], ah1, bl1[0], bl1[1]);
                mma_bf16(acc[8 + a0 + 3], ah1, bl1[2], bl1[3]);
                // term 3: Alo @ Bhi
                mma_bf16(acc[a0 + 0],     al0, bh0[0], bh0[1]);
                mma_bf16(acc[a0 + 1],     al0, bh0[2], bh0[3]);
                mma_bf16(acc[a0 + 2],     al0, bh1[0], bh1[1]);
                mma_bf16(acc[a0 + 3],     al0, bh1[2], bh1[3]);
                mma_bf16(acc[8 + a0 + 0], al1, bh0[0], bh0[1]);
                mma_bf16(acc[8 + a0 + 1], al1, bh0[2], bh0[3]);
                mma_bf16(acc[8 + a0 + 2], al1, bh1[0], bh1[1]);
                mma_bf16(acc[8 + a0 + 3], al1, bh1[2], bh1[3]);
            }
        }
    }

    // ---- epilogue: direct float2 stores (full 32B sectors) ----
    #pragma unroll
    for (int sub = 0; sub < 2; sub++) {
        int ra = r0g + sub * 16;
        int rb = ra + 8;
        #pragma unroll
        for (int nt = 0; nt < 8; nt++) {
            int gc = nh * 128 + n0 + nt * 8 + cq;
            const float* a = acc[sub * 8 + nt];
            float2 v0 = make_float2(a[0], a[1]);
            float2 v1 = make_float2(a[2], a[3]);
            if (gc < HALF) {
                if (ra < N_NODES) *(float2*)&xl[(size_t)ra * HALF + gc] = v0;
                if (rb < N_NODES) *(float2*)&xl[(size_t)rb * HALF + gc] = v1;
            } else {
                int g2 = gc - HALF;
                if (ra < N_NODES) *(float2*)&xr[(size_t)ra * HALF + g2] = v0;
                if (rb < N_NODES) *(float2*)&xr[(size_t)rb * HALF + g2] = v1;
            }
        }
    }
}

// ---------------- fused GATv2 softmax + aggregation (one warp per node) --
// Single pass, no max-subtraction (scores O(5), fp32-exp safe).
// MODE 0: fp32 out + bias. MODE 1: bias + ELU, output split bf16 hi/lo.
template <int H, int C, int MODE>
__global__ void agg_k(const float* __restrict__ xl, const float* __restrict__ xr,
                      const float* __restrict__ att, const float* __restrict__ bias,
                      float* __restrict__ outf,
                      __nv_bfloat16* __restrict__ ohi, __nv_bfloat16* __restrict__ olo) {
    constexpr int HC  = H * C;
    constexpr int VEC = HC / 32;       // 4 (layer1) or 2 (layer2)
    constexpr int LPH = C / VEC;       // lanes per head
    const int lane = threadIdx.x & 31;
    const int d = blockIdx.x * (blockDim.x >> 5) + (threadIdx.x >> 5);
    if (d >= N_NODES) return;
    const int base = lane * VEC;

    float xrv[VEC], attv[VEC];
    #pragma unroll
    for (int v = 0; v < VEC; v++) {
        xrv[v]  = xr[(size_t)d * HC + base + v];
        attv[v] = att[base + v];
    }
    const int s0 = g_start[d], s1 = g_start[d + 1];

    float acc[VEC];
    #pragma unroll
    for (int v = 0; v < VEC; v++) acc[v] = 0.f;
    float den = 0.f;

    float xn[VEC];
    if (s0 < s1) {
        const float* xp = xl + (size_t)g_sorted[s0] * HC + base;
        if (VEC == 4) {
            float4 t = *(const float4*)xp;
            xn[0] = t.x; xn[1] = t.y; xn[2] = t.z; xn[3] = t.w;
        } else {
            float2 t = *(const float2*)xp;
            xn[0] = t.x; xn[1] = t.y;
        }
    }
    for (int j = s0; j < s1; j++) {
        float xv[VEC];
        #pragma unroll
        for (int v = 0; v < VEC; v++) xv[v] = xn[v];
        if (j + 1 < s1) {
            const float* xp = xl + (size_t)g_sorted[j + 1] * HC + base;
            if (VEC == 4) {
                float4 t = *(const float4*)xp;
                xn[0] = t.x; xn[1] = t.y; xn[2] = t.z; xn[3] = t.w;
            } else {
                float2 t = *(const float2*)xp;
                xn[0] = t.x; xn[1] = t.y;
            }
        }
        float s = 0.f;
        #pragma unroll
        for (int v = 0; v < VEC; v++) {
            float m = xv[v] + xrv[v];
            m = (m > 0.f) ? m : 0.2f * m;      // leaky_relu
            s = fmaf(m, attv[v], s);
        }
        #pragma unroll
        for (int w = LPH >> 1; w > 0; w >>= 1)
            s += __shfl_xor_sync(0xffffffffu, s, w);
        float p = __expf(s);
        den += p;
        #pragma unroll
        for (int v = 0; v < VEC; v++) acc[v] = fmaf(p, xv[v], acc[v]);
    }

    const float inv = 1.0f / den;       // self-loop guarantees den > 0
    if (MODE == 0) {
        #pragma unroll
        for (int v = 0; v < VEC; v++)
            outf[(size_t)d * HC + base + v] = acc[v] * inv + bias[base + v];
    } else {
        ushort hh[VEC], ll[VEC];
        #pragma unroll
        for (int v = 0; v < VEC; v++) {
            float r = acc[v] * inv + bias[base + v];
            r = (r > 0.f) ? r : (__expf(r) - 1.0f);   // ELU
            __nv_bfloat16 hb = __float2bfloat16_rn(r);
            hh[v] = __bfloat16_as_ushort(hb);
            ll[v] = __bfloat16_as_ushort(__float2bfloat16_rn(r - __bfloat162float(hb)));
        }
        size_t o = ((size_t)d * HC + base) >> 2;      // VEC==4: uint2 granules
        ((uint2*)ohi)[o] = *(const uint2*)hh;
        ((uint2*)olo)[o] = *(const uint2*)ll;
    }
}

// ---------------- launch ----------------
extern "C" void kernel_launch(void* const* d_in, const int* in_sizes, int n_in,
                              void* d_out, int out_size) {
    const float* x    = (const float*)d_in[0];
    const int*   ei   = (const int*)  d_in[1];
    const float* W1l  = (const float*)d_in[2];
    const float* W1r  = (const float*)d_in[3];
    const float* att1 = (const float*)d_in[4];
    const float* b1   = (const float*)d_in[5];
    const float* W2l  = (const float*)d_in[6];
    const float* W2r  = (const float*)d_in[7];
    const float* att2 = (const float*)d_in[8];
    const float* b2   = (const float*)d_in[9];
    float* out = (float*)d_out;

    float *xl1, *xr1, *xl2, *xr2;
    __nv_bfloat16 *hhi, *hlo, *b1hi, *b1lo, *b2hi, *b2lo;
    cudaGetSymbolAddress((void**)&xl1, g_xl1);
    cudaGetSymbolAddress((void**)&xr1, g_xr1);
    cudaGetSymbolAddress((void**)&hhi, g_hhi);
    cudaGetSymbolAddress((void**)&hlo, g_hlo);
    cudaGetSymbolAddress((void**)&xl2, g_xl2);
    cudaGetSymbolAddress((void**)&xr2, g_xr2);
    cudaGetSymbolAddress((void**)&b1hi, g_B1hi);
    cudaGetSymbolAddress((void**)&b1lo, g_B1lo);
    cudaGetSymbolAddress((void**)&b2hi, g_B2hi);
    cudaGetSymbolAddress((void**)&b2lo, g_B2lo);

    constexpr int SMEMB = 2 * 128 * 272 + 2 * 128 * 144;   // 106496
    cudaFuncSetAttribute(gemm_tc_k<128, true>,
                         cudaFuncAttributeMaxDynamicSharedMemorySize, SMEMB);
    cudaFuncSetAttribute(gemm_tc_k<64, false>,
                         cudaFuncAttributeMaxDynamicSharedMemorySize, SMEMB);

    const int ETB = (N_ET + 255) / 256;
    const int GT  = (N_NODES + 127) / 128;   // 391 gemm tiles

    // NOTE: gemm1 placed 4th — the ncu capture slot — for visibility.
    zero_cnt_k<<<148, 256>>>();
    hist_k<<<ETB, 256>>>(ei);
    bimg_k<<<192, 256>>>(W1l, W1r, W2l, W2r);
    gemm_tc_k<128, true><<<dim3(GT, 2), 256, SMEMB>>>(x, nullptr, nullptr,
                                                      b1hi, b1lo, xl1, xr1);
    scan1_k<<<NB_SCAN, 256>>>();
    scan2_k<<<1, 256>>>();
    scan3_k<<<NB_SCAN, 256>>>();
    scatter_k<<<ETB, 256>>>(ei);

    agg_k<4, 32, 1><<<(N_NODES + 7) / 8, 256>>>(xl1, xr1, att1, b1,
                                                nullptr, hhi, hlo);
    gemm_tc_k<64, false><<<dim3(GT, 1), 256, SMEMB>>>(nullptr, hhi, hlo,
                                                      b2hi, b2lo, xl2, xr2);
    agg_k<1, 64, 0><<<(N_NODES + 7) / 8, 256>>>(xl2, xr2, att2, b2,
                                                out, nullptr, nullptr);
}

// round 14
// speedup vs baseline: 1.3202x; 1.0738x over previous
#include <cuda_runtime.h>
#include <cuda_bf16.h>
#include <math.h>
#include <stdint.h>

#define N_NODES 50000
#define N_EDGES 500000
#define N_ET    (N_NODES + N_EDGES)   // 550000 edges incl. self-loops
#define NB_SCAN ((N_NODES + 255) / 256)   // 196 scan blocks

// ---------------- static scratch (no allocations allowed) ----------------
__device__ float g_xl1[N_NODES * 128];
__device__ float g_xr1[N_NODES * 128];
__device__ __nv_bfloat16 g_hhi[N_NODES * 128];
__device__ __nv_bfloat16 g_hlo[N_NODES * 128];
__device__ float g_xl2[N_NODES * 64];
__device__ float g_xr2[N_NODES * 64];
__device__ int   g_cnt   [N_NODES];
__device__ int   g_start [N_NODES + 1];
__device__ int   g_cursor[N_NODES];
__device__ int   g_sorted[N_ET];
__device__ int   g_bsum  [256];
// bf16 weight images, plain [n][k] row-major (ldmatrix-native for B operand)
__device__ __nv_bfloat16 g_B1hi[256 * 128];
__device__ __nv_bfloat16 g_B1lo[256 * 128];
__device__ __nv_bfloat16 g_B2hi[128 * 128];
__device__ __nv_bfloat16 g_B2lo[128 * 128];

// ---------------- counting sort of edges by destination ----------------
__global__ void zero_cnt_k() {
    for (int i = blockIdx.x * blockDim.x + threadIdx.x; i < N_NODES;
         i += gridDim.x * blockDim.x)
        g_cnt[i] = 0;
}
__device__ __forceinline__ int edge_dst(const int* __restrict__ ei, int e) {
    return (e < N_EDGES) ? ei[N_EDGES + e] : (e - N_EDGES);
}
__device__ __forceinline__ int edge_src(const int* __restrict__ ei, int e) {
    return (e < N_EDGES) ? ei[e] : (e - N_EDGES);
}
__global__ void hist_k(const int* __restrict__ ei) {
    int e = blockIdx.x * blockDim.x + threadIdx.x;
    if (e < N_ET) atomicAdd(&g_cnt[edge_dst(ei, e)], 1);
}

// ---------------- three-phase multi-block exclusive scan ----------------
__global__ void scan1_k() {               // per-block reduction
    __shared__ int sh[256];
    int i = blockIdx.x * 256 + threadIdx.x;
    int v = (i < N_NODES) ? g_cnt[i] : 0;
    sh[threadIdx.x] = v;
    __syncthreads();
    #pragma unroll
    for (int d = 128; d > 0; d >>= 1) {
        if (threadIdx.x < d) sh[threadIdx.x] += sh[threadIdx.x + d];
        __syncthreads();
    }
    if (threadIdx.x == 0) g_bsum[blockIdx.x] = sh[0];
}
__global__ void scan2_k() {               // scan the 196 block sums
    __shared__ int sh[256];
    int t = threadIdx.x;
    int v = (t < NB_SCAN) ? g_bsum[t] : 0;
    sh[t] = v;
    __syncthreads();
    #pragma unroll
    for (int d = 1; d < 256; d <<= 1) {
        int u = (t >= d) ? sh[t - d] : 0;
        __syncthreads();
        sh[t] += u;
        __syncthreads();
    }
    if (t < NB_SCAN) g_bsum[t] = sh[t] - v;   // exclusive
    if (t == 0) g_start[N_NODES] = N_ET;
}
__global__ void scan3_k() {               // per-block exclusive scan + offset
    __shared__ int sh[256];
    int t = threadIdx.x;
    int i = blockIdx.x * 256 + t;
    int v = (i < N_NODES) ? g_cnt[i] : 0;
    sh[t] = v;
    __syncthreads();
    #pragma unroll
    for (int d = 1; d < 256; d <<= 1) {
        int u = (t >= d) ? sh[t - d] : 0;
        __syncthreads();
        sh[t] += u;
        __syncthreads();
    }
    int ex = sh[t] - v + g_bsum[blockIdx.x];
    if (i < N_NODES) { g_start[i] = ex; g_cursor[i] = ex; }
}

__global__ void scatter_k(const int* __restrict__ ei) {
    int e = blockIdx.x * blockDim.x + threadIdx.x;
    if (e < N_ET) {
        int d = edge_dst(ei, e);
        int s = edge_src(ei, e);
        int pos = atomicAdd(&g_cursor[d], 1);
        g_sorted[pos] = s;
    }
}

// ---------------- weight -> bf16 hi/lo images, [n][k] row-major ----------
__global__ void bimg_k(const float* __restrict__ W1l, const float* __restrict__ W1r,
                       const float* __restrict__ W2l, const float* __restrict__ W2r) {
    int t = blockIdx.x * blockDim.x + threadIdx.x;
    if (t < 256 * 128) {                    // layer 1
        int n = t >> 7, k = t & 127;
        float v = (n < 128) ? W1l[k * 128 + n] : W1r[k * 128 + (n - 128)];
        __nv_bfloat16 h = __float2bfloat16_rn(v);
        g_B1hi[n * 128 + k] = h;
        g_B1lo[n * 128 + k] = __float2bfloat16_rn(v - __bfloat162float(h));
    } else if (t < 256 * 128 + 128 * 128) { // layer 2
        int t2 = t - 256 * 128;
        int n = t2 >> 7, k = t2 & 127;
        float v = (n < 64) ? W2l[k * 64 + n] : W2r[k * 64 + (n - 64)];
        __nv_bfloat16 h = __float2bfloat16_rn(v);
        g_B2hi[n * 128 + k] = h;
        g_B2lo[n * 128 + k] = __float2bfloat16_rn(v - __bfloat162float(h));
    }
}

// ---------------- mma.sync helpers (sm_80 baseline, works on sm_103) -----
__device__ __forceinline__ void ldsm_x4(uint32_t* r, uint32_t addr) {
    asm volatile("ldmatrix.sync.aligned.m8n8.x4.shared.b16 {%0,%1,%2,%3}, [%4];"
        : "=r"(r[0]), "=r"(r[1]), "=r"(r[2]), "=r"(r[3]) : "r"(addr));
}
__device__ __forceinline__ void mma_bf16(float* d, const uint32_t* a,
                                         uint32_t b0, uint32_t b1) {
    asm volatile("mma.sync.aligned.m16n8k16.row.col.f32.bf16.bf16.f32 "
        "{%0,%1,%2,%3}, {%4,%5,%6,%7}, {%8,%9}, {%0,%1,%2,%3};"
        : "+f"(d[0]), "+f"(d[1]), "+f"(d[2]), "+f"(d[3])
        : "r"(a[0]), "r"(a[1]), "r"(a[2]), "r"(a[3]), "r"(b0), "r"(b1));
}

// ---------------- HMMA split-bf16 dual GEMM (3 blocks/SM) ----------------
// D[128, 64] = Ahi@Bhi + Ahi@Blo + Alo@Bhi, fp32 accum.
// blockIdx.y = 64-col quarter. Block tile 128x64, warp tile 32x32
// (8 warps = 4 row-groups x 2 col-groups). Both A and B staged in half-K
// chunks (144-B rows): 55.3 KB smem + <=85 regs -> 3 blocks/SM, occ 37.5%.
template <int HALF, bool CONVERT>
__global__ void __launch_bounds__(256, 3)
gemm_tc_k(const float* __restrict__ xf,
          const __nv_bfloat16* __restrict__ ahi_g,
          const __nv_bfloat16* __restrict__ alo_g,
          const __nv_bfloat16* __restrict__ bhi_img,
          const __nv_bfloat16* __restrict__ blo_img,
          float* __restrict__ xl, float* __restrict__ xr) {
    extern __shared__ char smem[];
    constexpr int STRH = 144;                 // row: 72 bf16 (64 data + pad)
    constexpr int A_HI = 0;
    constexpr int A_LO = A_HI + 128 * STRH;   // 18432
    constexpr int B_HI = A_LO + 128 * STRH;   // 36864
    constexpr int B_LO = B_HI + 64 * STRH;    // 46080  (total 55296)
    const int tid = threadIdx.x, wid = tid >> 5, lane = tid & 31;
    const int row0 = blockIdx.x * 128;
    const int nq   = blockIdx.y;              // 64-col quarter
    uint32_t sb;
    asm("{ .reg .u64 t; cvta.to.shared.u64 t, %1; cvt.u32.u64 %0, t; }"
        : "=r"(sb) : "l"(smem));

    // warp-tile addressing: wr = row group (32 rows), wc = col group (32 cols)
    const int wr = wid & 3, wc = wid >> 2;
    const int m0 = wr * 32;
    const int n0 = wc * 32;
    uint32_t aRow = m0 + (lane & 15);
    uint32_t aCol = (lane >> 4) * 16;              // bytes
    uint32_t aAddrH = sb + A_HI + aRow * STRH + aCol;
    uint32_t aAddrL = sb + A_LO + aRow * STRH + aCol;
    int g = lane >> 3;
    uint32_t bRow = n0 + (lane & 7) + ((g & 2) << 2);
    uint32_t bCol = (g & 1) * 16;                  // bytes
    uint32_t bAddrH = sb + B_HI + bRow * STRH + bCol;
    uint32_t bAddrL = sb + B_LO + bRow * STRH + bCol;
    const int rq = lane >> 2;
    const int cq = (lane & 3) * 2;
    const int r0g = row0 + m0 + rq;

    const uint4* bs1 = (const uint4*)bhi_img;
    const uint4* bs2 = (const uint4*)blo_img;

    float acc[8][4];     // [sub*4 + n8tile][quad] ; sub = row subtile (0/1)
    #pragma unroll
    for (int i = 0; i < 8; i++)
        #pragma unroll
        for (int j = 0; j < 4; j++) acc[i][j] = 0.f;

    #pragma unroll 1
    for (int kh = 0; kh < 2; kh++) {
        if (kh) __syncthreads();          // all warps done reading chunk 0
        // ---- A half-K chunk ----
        if (CONVERT) {
            const float4* xt = (const float4*)(xf + (size_t)row0 * 128);
            for (int idx = tid; idx < 2048; idx += 256) {
                int r = idx >> 4, k4 = idx & 15, c0 = k4 * 4;
                float4 v = make_float4(0.f, 0.f, 0.f, 0.f);
                if (row0 + r < N_NODES) v = xt[r * 32 + kh * 16 + k4];
                __nv_bfloat16 h0 = __float2bfloat16_rn(v.x);
                __nv_bfloat16 h1 = __float2bfloat16_rn(v.y);
                __nv_bfloat16 h2 = __float2bfloat16_rn(v.z);
                __nv_bfloat16 h3 = __float2bfloat16_rn(v.w);
                ushort hh[4] = { __bfloat16_as_ushort(h0), __bfloat16_as_ushort(h1),
                                 __bfloat16_as_ushort(h2), __bfloat16_as_ushort(h3) };
                ushort ll[4] = {
                    __bfloat16_as_ushort(__float2bfloat16_rn(v.x - __bfloat162float(h0))),
                    __bfloat16_as_ushort(__float2bfloat16_rn(v.y - __bfloat162float(h1))),
                    __bfloat16_as_ushort(__float2bfloat16_rn(v.z - __bfloat162float(h2))),
                    __bfloat16_as_ushort(__float2bfloat16_rn(v.w - __bfloat162float(h3))) };
                *(uint2*)(smem + A_HI + r * STRH + c0 * 2) = *(const uint2*)hh;
                *(uint2*)(smem + A_LO + r * STRH + c0 * 2) = *(const uint2*)ll;
            }
        } else {
            const uint4* s1 = (const uint4*)ahi_g;
            const uint4* s2 = (const uint4*)alo_g;
            for (int idx = tid; idx < 1024; idx += 256) {
                int r = idx >> 3, seg = idx & 7;
                uint4 v1 = make_uint4(0u, 0u, 0u, 0u), v2 = v1;
                if (row0 + r < N_NODES) {
                    v1 = s1[(size_t)(row0 + r) * 16 + kh * 8 + seg];
                    v2 = s2[(size_t)(row0 + r) * 16 + kh * 8 + seg];
                }
                *(uint4*)(smem + A_HI + r * STRH + seg * 16) = v1;
                *(uint4*)(smem + A_LO + r * STRH + seg * 16) = v2;
            }
        }
        // ---- B half-K chunk: rows nq*64..+64, k in [kh*64, kh*64+64) ----
        for (int i = tid; i < 64 * 8; i += 256) {
            int r = i >> 3, seg = i & 7;
            *(uint4*)(smem + B_HI + r * STRH + seg * 16) =
                bs1[(nq * 64 + r) * 16 + kh * 8 + seg];
            *(uint4*)(smem + B_LO + r * STRH + seg * 16) =
                bs2[(nq * 64 + r) * 16 + kh * 8 + seg];
        }
        __syncthreads();

        #pragma unroll
        for (int ks = 0; ks < 4; ks++) {
            uint32_t ko = ks * 32;             // byte offset within chunk
            uint32_t ah0[4], ah1[4], al0[4], al1[4];
            ldsm_x4(ah0, aAddrH + ko);
            ldsm_x4(ah1, aAddrH + 16 * STRH + ko);
            ldsm_x4(al0, aAddrL + ko);
            ldsm_x4(al1, aAddrL + 16 * STRH + ko);
            uint32_t bh0[4], bh1[4], bl0[4], bl1[4];
            ldsm_x4(bh0, bAddrH + ko);
            ldsm_x4(bh1, bAddrH + 16 * STRH + ko);
            ldsm_x4(bl0, bAddrL + ko);
            ldsm_x4(bl1, bAddrL + 16 * STRH + ko);
            // term 1: Ahi @ Bhi  (8 independent accs)
            mma_bf16(acc[0], ah0, bh0[0], bh0[1]);
            mma_bf16(acc[1], ah0, bh0[2], bh0[3]);
            mma_bf16(acc[2], ah0, bh1[0], bh1[1]);
            mma_bf16(acc[3], ah0, bh1[2], bh1[3]);
            mma_bf16(acc[4], ah1, bh0[0], bh0[1]);
            mma_bf16(acc[5], ah1, bh0[2], bh0[3]);
            mma_bf16(acc[6], ah1, bh1[0], bh1[1]);
            mma_bf16(acc[7], ah1, bh1[2], bh1[3]);
            // term 2: Ahi @ Blo
            mma_bf16(acc[0], ah0, bl0[0], bl0[1]);
            mma_bf16(acc[1], ah0, bl0[2], bl0[3]);
            mma_bf16(acc[2], ah0, bl1[0], bl1[1]);
            mma_bf16(acc[3], ah0, bl1[2], bl1[3]);
            mma_bf16(acc[4], ah1, bl0[0], bl0[1]);
            mma_bf16(acc[5], ah1, bl0[2], bl0[3]);
            mma_bf16(acc[6], ah1, bl1[0], bl1[1]);
            mma_bf16(acc[7], ah1, bl1[2], bl1[3]);
            // term 3: Alo @ Bhi
            mma_bf16(acc[0], al0, bh0[0], bh0[1]);
            mma_bf16(acc[1], al0, bh0[2], bh0[3]);
            mma_bf16(acc[2], al0, bh1[0], bh1[1]);
            mma_bf16(acc[3], al0, bh1[2], bh1[3]);
            mma_bf16(acc[4], al1, bh0[0], bh0[1]);
            mma_bf16(acc[5], al1, bh0[2], bh0[3]);
            mma_bf16(acc[6], al1, bh1[0], bh1[1]);
            mma_bf16(acc[7], al1, bh1[2], bh1[3]);
        }
    }

    // ---- epilogue: direct float2 stores (full 32B sectors) ----
    #pragma unroll
    for (int sub = 0; sub < 2; sub++) {
        int ra = r0g + sub * 16;
        int rb = ra + 8;
        #pragma unroll
        for (int nt = 0; nt < 4; nt++) {
            int gc = nq * 64 + n0 + nt * 8 + cq;
            const float* a = acc[sub * 4 + nt];
            float2 v0 = make_float2(a[0], a[1]);
            float2 v1 = make_float2(a[2], a[3]);
            if (gc < HALF) {
                if (ra < N_NODES) *(float2*)&xl[(size_t)ra * HALF + gc] = v0;
                if (rb < N_NODES) *(float2*)&xl[(size_t)rb * HALF + gc] = v1;
            } else {
                int g2 = gc - HALF;
                if (ra < N_NODES) *(float2*)&xr[(size_t)ra * HALF + g2] = v0;
                if (rb < N_NODES) *(float2*)&xr[(size_t)rb * HALF + g2] = v1;
            }
        }
    }
}

// ---------------- fused GATv2 softmax + aggregation (one warp per node) --
// Single pass, no max-subtraction (scores O(5), fp32-exp safe).
// MODE 0: fp32 out + bias. MODE 1: bias + ELU, output split bf16 hi/lo.
template <int H, int C, int MODE>
__global__ void agg_k(const float* __restrict__ xl, const float* __restrict__ xr,
                      const float* __restrict__ att, const float* __restrict__ bias,
                      float* __restrict__ outf,
                      __nv_bfloat16* __restrict__ ohi, __nv_bfloat16* __restrict__ olo) {
    constexpr int HC  = H * C;
    constexpr int VEC = HC / 32;       // 4 (layer1) or 2 (layer2)
    constexpr int LPH = C / VEC;       // lanes per head
    const int lane = threadIdx.x & 31;
    const int d = blockIdx.x * (blockDim.x >> 5) + (threadIdx.x >> 5);
    if (d >= N_NODES) return;
    const int base = lane * VEC;

    float xrv[VEC], attv[VEC];
    #pragma unroll
    for (int v = 0; v < VEC; v++) {
        xrv[v]  = xr[(size_t)d * HC + base + v];
        attv[v] = att[base + v];
    }
    const int s0 = g_start[d], s1 = g_start[d + 1];

    float acc[VEC];
    #pragma unroll
    for (int v = 0; v < VEC; v++) acc[v] = 0.f;
    float den = 0.f;

    float xn[VEC];
    if (s0 < s1) {
        const float* xp = xl + (size_t)g_sorted[s0] * HC + base;
        if (VEC == 4) {
            float4 t = *(const float4*)xp;
            xn[0] = t.x; xn[1] = t.y; xn[2] = t.z; xn[3] = t.w;
        } else {
            float2 t = *(const float2*)xp;
            xn[0] = t.x; xn[1] = t.y;
        }
    }
    for (int j = s0; j < s1; j++) {
        float xv[VEC];
        #pragma unroll
        for (int v = 0; v < VEC; v++) xv[v] = xn[v];
        if (j + 1 < s1) {
            const float* xp = xl + (size_t)g_sorted[j + 1] * HC + base;
            if (VEC == 4) {
                float4 t = *(const float4*)xp;
                xn[0] = t.x; xn[1] = t.y; xn[2] = t.z; xn[3] = t.w;
            } else {
                float2 t = *(const float2*)xp;
                xn[0] = t.x; xn[1] = t.y;
            }
        }
        float s = 0.f;
        #pragma unroll
        for (int v = 0; v < VEC; v++) {
            float m = xv[v] + xrv[v];
            m = (m > 0.f) ? m : 0.2f * m;      // leaky_relu
            s = fmaf(m, attv[v], s);
        }
        #pragma unroll
        for (int w = LPH >> 1; w > 0; w >>= 1)
            s += __shfl_xor_sync(0xffffffffu, s, w);
        float p = __expf(s);
        den += p;
        #pragma unroll
        for (int v = 0; v < VEC; v++) acc[v] = fmaf(p, xv[v], acc[v]);
    }

    const float inv = 1.0f / den;       // self-loop guarantees den > 0
    if (MODE == 0) {
        #pragma unroll
        for (int v = 0; v < VEC; v++)
            outf[(size_t)d * HC + base + v] = acc[v] * inv + bias[base + v];
    } else {
        ushort hh[VEC], ll[VEC];
        #pragma unroll
        for (int v = 0; v < VEC; v++) {
            float r = acc[v] * inv + bias[base + v];
            r = (r > 0.f) ? r : (__expf(r) - 1.0f);   // ELU
            __nv_bfloat16 hb = __float2bfloat16_rn(r);
            hh[v] = __bfloat16_as_ushort(hb);
            ll[v] = __bfloat16_as_ushort(__float2bfloat16_rn(r - __bfloat162float(hb)));
        }
        size_t o = ((size_t)d * HC + base) >> 2;      // VEC==4: uint2 granules
        ((uint2*)ohi)[o] = *(const uint2*)hh;
        ((uint2*)olo)[o] = *(const uint2*)ll;
    }
}

// ---------------- launch ----------------
extern "C" void kernel_launch(void* const* d_in, const int* in_sizes, int n_in,
                              void* d_out, int out_size) {
    const float* x    = (const float*)d_in[0];
    const int*   ei   = (const int*)  d_in[1];
    const float* W1l  = (const float*)d_in[2];
    const float* W1r  = (const float*)d_in[3];
    const float* att1 = (const float*)d_in[4];
    const float* b1   = (const float*)d_in[5];
    const float* W2l  = (const float*)d_in[6];
    const float* W2r  = (const float*)d_in[7];
    const float* att2 = (const float*)d_in[8];
    const float* b2   = (const float*)d_in[9];
    float* out = (float*)d_out;

    float *xl1, *xr1, *xl2, *xr2;
    __nv_bfloat16 *hhi, *hlo, *b1hi, *b1lo, *b2hi, *b2lo;
    cudaGetSymbolAddress((void**)&xl1, g_xl1);
    cudaGetSymbolAddress((void**)&xr1, g_xr1);
    cudaGetSymbolAddress((void**)&hhi, g_hhi);
    cudaGetSymbolAddress((void**)&hlo, g_hlo);
    cudaGetSymbolAddress((void**)&xl2, g_xl2);
    cudaGetSymbolAddress((void**)&xr2, g_xr2);
    cudaGetSymbolAddress((void**)&b1hi, g_B1hi);
    cudaGetSymbolAddress((void**)&b1lo, g_B1lo);
    cudaGetSymbolAddress((void**)&b2hi, g_B2hi);
    cudaGetSymbolAddress((void**)&b2lo, g_B2lo);

    constexpr int SMEMB = 2 * 128 * 144 + 2 * 64 * 144;   // 55296
    cudaFuncSetAttribute(gemm_tc_k<128, true>,
                         cudaFuncAttributeMaxDynamicSharedMemorySize, SMEMB);
    cudaFuncSetAttribute(gemm_tc_k<64, false>,
                         cudaFuncAttributeMaxDynamicSharedMemorySize, SMEMB);

    const int ETB = (N_ET + 255) / 256;
    const int GT  = (N_NODES + 127) / 128;   // 391 gemm tiles

    // NOTE: gemm1 placed 4th — the ncu capture slot — for visibility.
    zero_cnt_k<<<148, 256>>>();
    hist_k<<<ETB, 256>>>(ei);
    bimg_k<<<192, 256>>>(W1l, W1r, W2l, W2r);
    gemm_tc_k<128, true><<<dim3(GT, 4), 256, SMEMB>>>(x, nullptr, nullptr,
                                                      b1hi, b1lo, xl1, xr1);
    scan1_k<<<NB_SCAN, 256>>>();
    scan2_k<<<1, 256>>>();
    scan3_k<<<NB_SCAN, 256>>>();
    scatter_k<<<ETB, 256>>>(ei);

    agg_k<4, 32, 1><<<(N_NODES + 7) / 8, 256>>>(xl1, xr1, att1, b1,
                                                nullptr, hhi, hlo);
    gemm_tc_k<64, false><<<dim3(GT, 2), 256, SMEMB>>>(nullptr, hhi, hlo,
                                                      b2hi, b2lo, xl2, xr2);
    agg_k<1, 64, 0><<<(N_NODES + 7) / 8, 256>>>(xl2, xr2, att2, b2,
                                                out, nullptr, nullptr);
}